// round 13
// baseline (speedup 1.0000x reference)
#include <cuda_runtime.h>
#include <cuda_bf16.h>
#include <math.h>
#include <cstdint>

#define BATCH 2
#define SEQ 2048
#define DMODEL 2048
#define NH 16
#define NKV 4
#define HD 128
#define NREP 4
#define QKV_OUT 3072   // (16 + 2*4) * 128
#define BSTOT (BATCH*SEQ)

// ---------------- scratch (device globals; no allocation allowed) ----------
__device__ float g_qkv  [BSTOT * QKV_OUT];        // 48 MB
__device__ float g_q    [BATCH * NH  * SEQ * HD]; // 32 MB (tf32, k-perm)
__device__ float g_k    [BATCH * NKV * SEQ * HD]; //  8 MB (tf32, k-perm)
__device__ float g_v    [BATCH * NKV * SEQ * HD]; //  8 MB (tf32)
__device__ float g_gate [BSTOT * NH];             // 0.5 MB
__device__ float g_attn [BSTOT * (NH*HD)];        // 32 MB (tf32, k-perm)
__device__ float2 g_rope[SEQ * 64];               // 1 MB
__device__ float g_xr   [BSTOT * DMODEL];         // 32 MB (x, tf32, k-perm)
__device__ float g_wqkvr[QKV_OUT * DMODEL];       // 24 MB (w_qkv, tf32, k-perm)
__device__ float g_wor  [DMODEL * DMODEL];        // 16 MB (w_o, tf32, k-perm)

// ========================== helpers ========================================
__device__ __forceinline__ float tf32r_(float x) {
    uint32_t r;
    asm("cvt.rna.tf32.f32 %0, %1;" : "=r"(r) : "f"(x));
    return __uint_as_float(r);
}
__device__ __forceinline__ float4 tf32r4_(float4 v) {
    v.x = tf32r_(v.x); v.y = tf32r_(v.y);
    v.z = tf32r_(v.z); v.w = tf32r_(v.w);
    return v;
}
__device__ __forceinline__ uint32_t smem_u32_(const void* p) {
    uint32_t a;
    asm("{ .reg .u64 t; cvta.to.shared.u64 t, %1; cvt.u32.u64 %0, t; }"
        : "=r"(a) : "l"(p));
    return a;
}
__device__ __forceinline__ void cpa16_(uint32_t dst, const void* src) {
    asm volatile("cp.async.cg.shared.global [%0], [%1], 16;"
                 :: "r"(dst), "l"(src));
}
#define CP_COMMIT() asm volatile("cp.async.commit_group;" ::: "memory")
#define CP_WAIT0()  asm volatile("cp.async.wait_group 0;" ::: "memory")
#define CP_WAIT1()  asm volatile("cp.async.wait_group 1;" ::: "memory")
#define CP_WAIT2()  asm volatile("cp.async.wait_group 2;" ::: "memory")

// D += A(16x8,row) * B(8x8,col)  tf32 inputs, f32 accum
__device__ __forceinline__ void mma_tf32_(float* d, const uint32_t* a,
                                          const uint32_t* b) {
    asm volatile(
        "mma.sync.aligned.m16n8k8.row.col.f32.tf32.tf32.f32 "
        "{%0,%1,%2,%3}, {%4,%5,%6,%7}, {%8,%9}, {%0,%1,%2,%3};\n"
        : "+f"(d[0]), "+f"(d[1]), "+f"(d[2]), "+f"(d[3])
        : "r"(a[0]), "r"(a[1]), "r"(a[2]), "r"(a[3]),
          "r"(b[0]), "r"(b[1]));
}

// k-group permutation: within each 8-elem group, k -> (k%4)*2 + k/4
// so pairs (k, k+4) become adjacent -> float2 fragment loads.
__device__ __forceinline__ int kperm_(int k) {
    return (k & ~7) + ((k & 3) << 1) + ((k & 7) >> 2);
}

// ================= round to tf32 + k-permute (flat, rows mult of 8) ========
__global__ __launch_bounds__(256)
void round_perm(const float* __restrict__ in, float* __restrict__ out, int n4) {
    int idx = blockIdx.x * 256 + threadIdx.x;
    if (idx >= n4) return;
    float4 v = ((const float4*)in)[idx];
    float vals[4] = { v.x, v.y, v.z, v.w };
    int e = idx * 4;
#pragma unroll
    for (int j = 0; j < 4; ++j)
        out[kperm_(e + j)] = tf32r_(vals[j]);
}

// ======================= rope table: cos/sin per (s,i) =====================
__global__ __launch_bounds__(256)
void rope_table(float2* __restrict__ tab) {
    int idx = blockIdx.x * 256 + threadIdx.x;
    int s = idx >> 6, i = idx & 63;
    float inv_freq = exp2f(-(float)(2 * i) * (1.0f / 128.0f)
                           * 13.28771237954945f);
    float sn, cs;
    sincosf((float)s * inv_freq, &sn, &cs);
    tab[idx] = make_float2(cs, sn);
}

// ===== tf32 mma.sync NT GEMM, cp.async 3-stage, pre-rounded k-perm inputs ==
// 128x128 CTA tile, BK=16, 8 warps (warp tile 32x64), pitch-20 smem.
#define GP 20
#define GSTW (128 * GP)
#define GSTAGE (2 * GSTW)
#define GEMM_SMEM (3 * GSTAGE * 4)  // 61440 bytes

__global__ __launch_bounds__(256, 2)
void gemm_tf32mma(const float* __restrict__ A, const float* __restrict__ Bm,
                  float* __restrict__ C, int M, int N, int K) {
    extern __shared__ float smg[];
    const uint32_t sb = smem_u32_(smg);

    const int tid  = threadIdx.x;
    const int lane = tid & 31;
    const int wid  = tid >> 5;
    const int wm   = wid & 3;
    const int wn   = wid >> 2;
    const int m0   = blockIdx.y * 128;
    const int n0   = blockIdx.x * 128;
    const int lg   = lane >> 2;
    const int lq   = lane & 3;

    float acc[2][8][4];
#pragma unroll
    for (int mt = 0; mt < 2; ++mt)
#pragma unroll
        for (int nt = 0; nt < 8; ++nt)
#pragma unroll
            for (int j = 0; j < 4; ++j) acc[mt][nt][j] = 0.f;

    const int row_ld = tid >> 2;
    const int c4_ld  = tid & 3;

    auto ISSUE = [&](int t) {
        const int st = (t % 3);
        const int k0 = t << 4;
        const uint32_t base = sb + (uint32_t)(st * GSTAGE) * 4;
#pragma unroll
        for (int i = 0; i < 2; ++i) {
            int row = row_ld + 64 * i;
            uint32_t off = (uint32_t)(row * GP + 4 * c4_ld) * 4;
            cpa16_(base + off,
                   A + (size_t)(m0 + row) * K + k0 + 4 * c4_ld);
            cpa16_(base + (uint32_t)GSTW * 4 + off,
                   Bm + (size_t)(n0 + row) * K + k0 + 4 * c4_ld);
        }
        CP_COMMIT();
    };

    auto COMPUTE = [&](int t) {
        const float* Sa = smg + (t % 3) * GSTAGE;
        const float* Sb = Sa + GSTW;
#pragma unroll
        for (int ks = 0; ks < 2; ++ks) {
            uint32_t af[2][4], bf[8][2];
#pragma unroll
            for (int mt = 0; mt < 2; ++mt) {
                const float* p = Sa + (wm * 32 + mt * 16 + lg) * GP
                               + ks * 8 + 2 * lq;
                float2 lo = *(const float2*)p;
                float2 hi = *(const float2*)(p + 8 * GP);
                af[mt][0] = __float_as_uint(lo.x);
                af[mt][2] = __float_as_uint(lo.y);
                af[mt][1] = __float_as_uint(hi.x);
                af[mt][3] = __float_as_uint(hi.y);
            }
#pragma unroll
            for (int nt = 0; nt < 8; ++nt) {
                const float* p = Sb + (wn * 64 + nt * 8 + lg) * GP
                               + ks * 8 + 2 * lq;
                float2 v = *(const float2*)p;
                bf[nt][0] = __float_as_uint(v.x);
                bf[nt][1] = __float_as_uint(v.y);
            }
#pragma unroll
            for (int mt = 0; mt < 2; ++mt)
#pragma unroll
                for (int nt = 0; nt < 8; ++nt)
                    mma_tf32_(acc[mt][nt], af[mt], bf[nt]);
        }
    };

    const int ntile = K >> 4;
    ISSUE(0);
    if (ntile > 1) ISSUE(1);
    for (int t = 0; t < ntile; ++t) {
        if (t + 2 < ntile) { ISSUE(t + 2); CP_WAIT2(); }
        else if (t + 1 < ntile) { CP_WAIT1(); }
        else { CP_WAIT0(); }
        __syncthreads();
        COMPUTE(t);
        __syncthreads();
    }

#pragma unroll
    for (int mt = 0; mt < 2; ++mt) {
        int r0 = m0 + wm * 32 + mt * 16 + lg;
#pragma unroll
        for (int nt = 0; nt < 8; ++nt) {
            int c = n0 + wn * 64 + nt * 8 + 2 * lq;
            *(float2*)(C + (size_t)r0 * N + c) =
                make_float2(acc[mt][nt][0], acc[mt][nt][1]);
            *(float2*)(C + (size_t)(r0 + 8) * N + c) =
                make_float2(acc[mt][nt][2], acc[mt][nt][3]);
        }
    }
}

// == RMSNorm + RoPE(table) + transpose; q/k written tf32-rounded + k-perm ===
__global__ __launch_bounds__(256)
void qkv_post(const float* __restrict__ qkv,
              const float* __restrict__ qw, const float* __restrict__ kw,
              const float2* __restrict__ rope,
              float* __restrict__ q_out, float* __restrict__ k_out,
              float* __restrict__ v_out) {
    const int gwarp = blockIdx.x * 8 + (threadIdx.x >> 5);
    const int lane  = threadIdx.x & 31;
    const int h  = gwarp % 24;
    const int bs = gwarp / 24;
    const int s  = bs & (SEQ - 1);
    const int b  = bs >> 11;

    float4 x = *(const float4*)(qkv + (size_t)bs * QKV_OUT + h * HD + 4 * lane);

    if (h < 20) {
        float ss = x.x * x.x + x.y * x.y + x.z * x.z + x.w * x.w;
#pragma unroll
        for (int o = 16; o; o >>= 1) ss += __shfl_xor_sync(~0u, ss, o);
        float rinv = rsqrtf(ss * (1.0f / HD) + 1e-5f);
        const float* wp = (h < 16) ? qw : kw;
        float4 w = *(const float4*)(wp + 4 * lane);
        x.x *= rinv * w.x; x.y *= rinv * w.y;
        x.z *= rinv * w.z; x.w *= rinv * w.w;
        float4 p;
        p.x = __shfl_xor_sync(~0u, x.x, 16);
        p.y = __shfl_xor_sync(~0u, x.y, 16);
        p.z = __shfl_xor_sync(~0u, x.z, 16);
        p.w = __shfl_xor_sync(~0u, x.w, 16);
        const int i0 = 4 * (lane & 15);
        const bool lo = lane < 16;
        float out[4], xv[4] = {x.x, x.y, x.z, x.w}, pv[4] = {p.x, p.y, p.z, p.w};
        const float2* rp = rope + s * 64 + i0;
#pragma unroll
        for (int j = 0; j < 4; ++j) {
            float2 cssn = rp[j];
            float x1 = lo ? xv[j] : pv[j];
            float x2 = lo ? pv[j] : xv[j];
            out[j] = lo ? (x1 * cssn.x - x2 * cssn.y)
                        : (x1 * cssn.y + x2 * cssn.x);
        }
        float* dst = (h < 16)
            ? q_out + (((size_t)b * NH + h) * SEQ + s) * HD
            : k_out + (((size_t)b * NKV + (h - 16)) * SEQ + s) * HD;
#pragma unroll
        for (int j = 0; j < 4; ++j) {
            int d = 4 * lane + j;
            dst[kperm_(d)] = tf32r_(out[j]);
        }
    } else {
        *(float4*)(v_out + (((size_t)b * NKV + (h - 20)) * SEQ + s) * HD + 4 * lane) =
            tf32r4_(x);
    }
}

// ========== gate = sigmoid(x . w_gate[h] + b), w_gate staged in smem =======
#define GATE_SMEM (NH * DMODEL * 4)   // 131072

__global__ __launch_bounds__(256)
void gate_kernel(const float* __restrict__ x, const float* __restrict__ wg,
                 const float* __restrict__ bg, float* __restrict__ gate) {
    extern __shared__ float ws[];
    const int tid = threadIdx.x;
    const int lane = tid & 31;
    const int warp = tid >> 5;
    for (int i = tid; i < NH * DMODEL / 4; i += 256)
        ((float4*)ws)[i] = ((const float4*)wg)[i];
    __syncthreads();

    const int r0 = blockIdx.x * 32;
#pragma unroll 1
    for (int rr = 0; rr < 4; ++rr) {
        const int row = r0 + warp + 8 * rr;
        const float4* xv = (const float4*)(x + (size_t)row * DMODEL);
        float acc[NH];
#pragma unroll
        for (int h = 0; h < NH; ++h) acc[h] = 0.f;
#pragma unroll 4
        for (int it = 0; it < 16; ++it) {
            int i4 = lane + 32 * it;
            float4 a = xv[i4];
#pragma unroll
            for (int h = 0; h < NH; ++h) {
                float4 w = ((const float4*)ws)[h * (DMODEL / 4) + i4];
                acc[h] += a.x * w.x + a.y * w.y + a.z * w.z + a.w * w.w;
            }
        }
#pragma unroll
        for (int h = 0; h < NH; ++h) {
            float v = acc[h];
#pragma unroll
            for (int o = 16; o; o >>= 1) v += __shfl_xor_sync(~0u, v, o);
            if (lane == 0)
                gate[(size_t)row * NH + h] =
                    1.0f / (1.0f + __expf(-(v + bg[h])));
        }
    }
}

// == causal flash attention (tf32 mma, k-perm Q/K float2 frags, cp.async) ===
// CTA: 64 q x 64 kv, 4 warps; 2 CTAs/SM.
#define FBM 64
#define FBN 64
#define FQP 136
#define FKP 136
#define FVP 136
#define FLASH_SMEM ((FBM*FQP + FBN*FKP + FBN*FVP) * 4)   // 104448 B

__global__ __launch_bounds__(128, 2)
void flash_mma(const float* __restrict__ Q, const float* __restrict__ Kt,
               const float* __restrict__ V, const float* __restrict__ gate,
               float* __restrict__ Oout) {
    extern __shared__ float sm[];
    float* Qs = sm;                       // [64][136]  (q, hd k-perm)
    float* Ks = Qs + FBM * FQP;           // [64][136]  (kv, hd k-perm)
    float* Vs = Ks + FBN * FKP;           // [64][136]  (kv, hd natural)
    const uint32_t sQ = smem_u32_(Qs);
    const uint32_t sK = smem_u32_(Ks);
    const uint32_t sV = smem_u32_(Vs);

    const int qt = blockIdx.x;
    const int h  = blockIdx.y;
    const int b  = blockIdx.z;
    const int kvh = h >> 2;
    const int tid = threadIdx.x;
    const int lane = tid & 31;
    const int w = tid >> 5;
    const int lg = lane >> 2;
    const int lq = lane & 3;
    const int q0 = qt * FBM;

    const float* Qg = Q  + (((size_t)b * NH + h) * SEQ + q0) * HD;
    const float* Kg = Kt + ((size_t)b * NKV + kvh) * SEQ * HD;
    const float* Vg = V  + ((size_t)b * NKV + kvh) * SEQ * HD;

    auto ISSUE_KV = [&](int t) {
        const int k0 = t * FBN;
#pragma unroll
        for (int i = 0; i < 16; ++i) {
            int idx = tid + 128 * i;
            int row = idx >> 5, c4 = idx & 31;
            cpa16_(sK + (uint32_t)(row * FKP + 4 * c4) * 4,
                   Kg + (size_t)(k0 + row) * HD + 4 * c4);
        }
#pragma unroll
        for (int i = 0; i < 16; ++i) {
            int idx = tid + 128 * i;
            int row = idx >> 5, c4 = idx & 31;
            cpa16_(sV + (uint32_t)(row * FVP + 4 * c4) * 4,
                   Vg + (size_t)(k0 + row) * HD + 4 * c4);
        }
        CP_COMMIT();
    };

    // prologue: Q + first K/V tile
    {
#pragma unroll
        for (int i = 0; i < 16; ++i) {
            int idx = tid + 128 * i;
            int row = idx >> 5, c4 = idx & 31;
            cpa16_(sQ + (uint32_t)(row * FQP + 4 * c4) * 4,
                   Qg + (size_t)row * HD + 4 * c4);
        }
        CP_COMMIT();
        ISSUE_KV(0);
        CP_WAIT0();
        __syncthreads();
    }

    float mi[2] = { -1e30f, -1e30f }, li[2] = { 0.f, 0.f };
    float o[16][4];
#pragma unroll
    for (int nt = 0; nt < 16; ++nt)
#pragma unroll
        for (int j = 0; j < 4; ++j) o[nt][j] = 0.f;

    const float scl = 0.08838834764831845f;   // 1/sqrt(128)
    const int nkt = qt + 1;

    for (int t = 0; t < nkt; ++t) {
        const int k0 = t * FBN;

        // ---- S = Q K^T (k-perm float2 fragment loads) ----
        float sc[8][4];
#pragma unroll
        for (int nt = 0; nt < 8; ++nt)
#pragma unroll
            for (int j = 0; j < 4; ++j) sc[nt][j] = 0.f;

#pragma unroll
        for (int ks = 0; ks < 16; ++ks) {
            const float* pa = Qs + (16 * w + lg) * FQP + 8 * ks + 2 * lq;
            float2 alo = *(const float2*)pa;
            float2 ahi = *(const float2*)(pa + 8 * FQP);
            uint32_t a[4];
            a[0] = __float_as_uint(alo.x);
            a[2] = __float_as_uint(alo.y);
            a[1] = __float_as_uint(ahi.x);
            a[3] = __float_as_uint(ahi.y);
#pragma unroll
            for (int nt = 0; nt < 8; ++nt) {
                const float* pb = Ks + (8 * nt + lg) * FKP + 8 * ks + 2 * lq;
                float2 bv = *(const float2*)pb;
                uint32_t bf[2];
                bf[0] = __float_as_uint(bv.x);
                bf[1] = __float_as_uint(bv.y);
                mma_tf32_(sc[nt], a, bf);
            }
        }

        // ---- scale + causal mask (only diagonal tile t == qt) ----
        const int qr0 = q0 + 16 * w + lg;
        const int qr1 = qr0 + 8;
        const bool needmask = (t == qt);
#pragma unroll
        for (int nt = 0; nt < 8; ++nt) {
            int c0 = k0 + 8 * nt + 2 * lq, c1 = c0 + 1;
            float s0 = sc[nt][0] * scl, s1 = sc[nt][1] * scl;
            float s2 = sc[nt][2] * scl, s3 = sc[nt][3] * scl;
            if (needmask) {
                if (c0 > qr0) s0 = -1e30f;
                if (c1 > qr0) s1 = -1e30f;
                if (c0 > qr1) s2 = -1e30f;
                if (c1 > qr1) s3 = -1e30f;
            }
            sc[nt][0] = s0; sc[nt][1] = s1; sc[nt][2] = s2; sc[nt][3] = s3;
        }

        // ---- online softmax ----
#pragma unroll
        for (int r = 0; r < 2; ++r) {
            float m = -1e30f;
#pragma unroll
            for (int nt = 0; nt < 8; ++nt)
                m = fmaxf(m, fmaxf(sc[nt][2 * r], sc[nt][2 * r + 1]));
            m = fmaxf(m, __shfl_xor_sync(~0u, m, 1));
            m = fmaxf(m, __shfl_xor_sync(~0u, m, 2));
            float newm = fmaxf(mi[r], m);
            float esc = __expf(mi[r] - newm);
            mi[r] = newm;
            float rs = 0.f;
#pragma unroll
            for (int nt = 0; nt < 8; ++nt) {
                float p0 = __expf(sc[nt][2 * r]     - newm);
                float p1 = __expf(sc[nt][2 * r + 1] - newm);
                sc[nt][2 * r] = p0; sc[nt][2 * r + 1] = p1;
                rs += p0 + p1;
            }
            rs += __shfl_xor_sync(~0u, rs, 1);
            rs += __shfl_xor_sync(~0u, rs, 2);
            li[r] = li[r] * esc + rs;
#pragma unroll
            for (int nt = 0; nt < 16; ++nt) {
                o[nt][2 * r]     *= esc;
                o[nt][2 * r + 1] *= esc;
            }
        }

        // ---- O += P V  (P frags via shuffles; V natural [kv][136]) ----
        const int src0 = (lane & ~3) | (lq >> 1);
        const int src1 = src0 + 2;
        const bool odd = lq & 1;
#pragma unroll
        for (int j = 0; j < 8; ++j) {
            float p00 = __shfl_sync(~0u, sc[j][0], src0);
            float p01 = __shfl_sync(~0u, sc[j][1], src0);
            float p02 = __shfl_sync(~0u, sc[j][2], src0);
            float p03 = __shfl_sync(~0u, sc[j][3], src0);
            float q00 = __shfl_sync(~0u, sc[j][0], src1);
            float q01 = __shfl_sync(~0u, sc[j][1], src1);
            float q02 = __shfl_sync(~0u, sc[j][2], src1);
            float q03 = __shfl_sync(~0u, sc[j][3], src1);
            uint32_t a[4];
            a[0] = __float_as_uint(tf32r_(odd ? p01 : p00));
            a[1] = __float_as_uint(tf32r_(odd ? p03 : p02));
            a[2] = __float_as_uint(tf32r_(odd ? q01 : q00));
            a[3] = __float_as_uint(tf32r_(odd ? q03 : q02));
            const float* pv0 = Vs + (8 * j + lq) * FVP + lg;
#pragma unroll
            for (int nt = 0; nt < 16; ++nt) {
                uint32_t bf[2];
                bf[0] = __float_as_uint(pv0[8 * nt]);
                bf[1] = __float_as_uint(pv0[4 * FVP + 8 * nt]);
                mma_tf32_(o[nt], a, bf);
            }
        }

        if (t + 1 < nkt) {
            __syncthreads();
            ISSUE_KV(t + 1);
            CP_WAIT0();
            __syncthreads();
        }
    }

    // ---- epilogue: /li, *gate, tf32-round + k-perm scatter to attn ----
#pragma unroll
    for (int r = 0; r < 2; ++r) {
        int row = q0 + 16 * w + lg + 8 * r;
        float g = gate[((size_t)b * SEQ + row) * NH + h];
        float inv = g / li[r];
        float* dst = Oout + ((size_t)(b * SEQ + row)) * (NH * HD) + h * HD;
#pragma unroll
        for (int nt = 0; nt < 16; ++nt) {
            int k0e = 2 * lq, k1e = 2 * lq + 1;
            int c0 = 8 * nt + ((k0e & 3) << 1) + (k0e >> 2);
            int c1 = 8 * nt + ((k1e & 3) << 1) + (k1e >> 2);
            dst[c0] = tf32r_(o[nt][2 * r] * inv);
            dst[c1] = tf32r_(o[nt][2 * r + 1] * inv);
        }
    }
}

// ================================ launch ===================================
extern "C" void kernel_launch(void* const* d_in, const int* in_sizes, int n_in,
                              void* d_out, int out_size) {
    const float* x      = (const float*)d_in[0];
    const float* w_qkv  = (const float*)d_in[1];
    const float* qnw    = (const float*)d_in[2];
    const float* knw    = (const float*)d_in[3];
    const float* w_gate = (const float*)d_in[4];
    const float* b_gate = (const float*)d_in[5];
    const float* w_o    = (const float*)d_in[6];
    float* out = (float*)d_out;

    float *qkv, *q, *k, *v, *gate, *attn, *xr, *wqkvr, *wor;
    float2* rope;
    cudaGetSymbolAddress((void**)&qkv,   g_qkv);
    cudaGetSymbolAddress((void**)&q,     g_q);
    cudaGetSymbolAddress((void**)&k,     g_k);
    cudaGetSymbolAddress((void**)&v,     g_v);
    cudaGetSymbolAddress((void**)&gate,  g_gate);
    cudaGetSymbolAddress((void**)&attn,  g_attn);
    cudaGetSymbolAddress((void**)&rope,  g_rope);
    cudaGetSymbolAddress((void**)&xr,    g_xr);
    cudaGetSymbolAddress((void**)&wqkvr, g_wqkvr);
    cudaGetSymbolAddress((void**)&wor,   g_wor);

    cudaFuncSetAttribute(gemm_tf32mma,
                         cudaFuncAttributeMaxDynamicSharedMemorySize, GEMM_SMEM);
    cudaFuncSetAttribute(flash_mma,
                         cudaFuncAttributeMaxDynamicSharedMemorySize, FLASH_SMEM);
    cudaFuncSetAttribute(gate_kernel,
                         cudaFuncAttributeMaxDynamicSharedMemorySize, GATE_SMEM);

    // 0) prep: rope table + tf32-round/k-permute GEMM operands
    rope_table<<<SEQ * 64 / 256, 256>>>(rope);
    round_perm<<<(BSTOT * DMODEL / 4) / 256, 256>>>(x, xr, BSTOT * DMODEL / 4);
    round_perm<<<(QKV_OUT * DMODEL / 4) / 256, 256>>>(w_qkv, wqkvr,
                                                      QKV_OUT * DMODEL / 4);
    round_perm<<<(DMODEL * DMODEL / 4) / 256, 256>>>(w_o, wor,
                                                     DMODEL * DMODEL / 4);
    // 1) QKV projection: [4096,2048] x [3072,2048]^T (pre-rounded, k-perm)
    {
        dim3 grid(QKV_OUT / 128, BSTOT / 128);
        gemm_tf32mma<<<grid, 256, GEMM_SMEM>>>(xr, wqkvr, qkv,
                                               BSTOT, QKV_OUT, DMODEL);
    }
    // 2) RMSNorm + RoPE(table) + layout (q/k tf32-rounded + k-perm)
    {
        qkv_post<<<(BSTOT * 24) / 8, 256>>>(qkv, qnw, knw, rope, q, k, v);
    }
    // 3) gate (w_gate staged in smem; reads original x)
    {
        gate_kernel<<<BSTOT / 32, 256, GATE_SMEM>>>(x, w_gate, b_gate, gate);
    }
    // 4) flash attention, tf32 mma (gated epilogue, writes rounded+perm attn)
    {
        dim3 grid(SEQ / FBM, NH, BATCH);
        flash_mma<<<grid, 128, FLASH_SMEM>>>(q, k, v, gate, attn);
    }
    // 5) output projection: [4096,2048] x [2048,2048]^T -> d_out
    {
        dim3 grid(DMODEL / 128, BSTOT / 128);
        gemm_tf32mma<<<grid, 256, GEMM_SMEM>>>(attn, wor, out,
                                               BSTOT, DMODEL, DMODEL);
    }
}

// round 14
// speedup vs baseline: 1.1506x; 1.1506x over previous
#include <cuda_runtime.h>
#include <cuda_bf16.h>
#include <math.h>
#include <cstdint>

#define BATCH 2
#define SEQ 2048
#define DMODEL 2048
#define NH 16
#define NKV 4
#define HD 128
#define NREP 4
#define QKV_OUT 3072   // (16 + 2*4) * 128
#define BSTOT (BATCH*SEQ)

// ---------------- scratch (device globals; no allocation allowed) ----------
__device__ float g_qkv  [BSTOT * QKV_OUT];        // 48 MB
__device__ float g_q    [BATCH * NH  * SEQ * HD]; // 32 MB (tf32, k-perm)
__device__ float g_k    [BATCH * NKV * SEQ * HD]; //  8 MB (tf32, k-perm)
__device__ float g_v    [BATCH * NKV * SEQ * HD]; //  8 MB (tf32)
__device__ float g_gate [BSTOT * NH];             // 0.5 MB
__device__ float g_attn [BSTOT * (NH*HD)];        // 32 MB (tf32, k-perm)
__device__ float2 g_rope[SEQ * 64];               // 1 MB
__device__ float g_xr   [BSTOT * DMODEL];         // 32 MB (x, tf32, k-perm)
__device__ float g_wqkvr[QKV_OUT * DMODEL];       // 24 MB (w_qkv, tf32, k-perm)
__device__ float g_wor  [DMODEL * DMODEL];        // 16 MB (w_o, tf32, k-perm)

// ========================== helpers ========================================
__device__ __forceinline__ float tf32r_(float x) {
    uint32_t r;
    asm("cvt.rna.tf32.f32 %0, %1;" : "=r"(r) : "f"(x));
    return __uint_as_float(r);
}
__device__ __forceinline__ float4 tf32r4_(float4 v) {
    v.x = tf32r_(v.x); v.y = tf32r_(v.y);
    v.z = tf32r_(v.z); v.w = tf32r_(v.w);
    return v;
}
__device__ __forceinline__ uint32_t smem_u32_(const void* p) {
    uint32_t a;
    asm("{ .reg .u64 t; cvta.to.shared.u64 t, %1; cvt.u32.u64 %0, t; }"
        : "=r"(a) : "l"(p));
    return a;
}
__device__ __forceinline__ void cpa16_(uint32_t dst, const void* src) {
    asm volatile("cp.async.cg.shared.global [%0], [%1], 16;"
                 :: "r"(dst), "l"(src));
}
#define CP_COMMIT() asm volatile("cp.async.commit_group;" ::: "memory")
#define CP_WAIT0()  asm volatile("cp.async.wait_group 0;" ::: "memory")
#define CP_WAIT1()  asm volatile("cp.async.wait_group 1;" ::: "memory")
#define CP_WAIT2()  asm volatile("cp.async.wait_group 2;" ::: "memory")

// D += A(16x8,row) * B(8x8,col)  tf32 inputs, f32 accum
__device__ __forceinline__ void mma_tf32_(float* d, const uint32_t* a,
                                          const uint32_t* b) {
    asm volatile(
        "mma.sync.aligned.m16n8k8.row.col.f32.tf32.tf32.f32 "
        "{%0,%1,%2,%3}, {%4,%5,%6,%7}, {%8,%9}, {%0,%1,%2,%3};\n"
        : "+f"(d[0]), "+f"(d[1]), "+f"(d[2]), "+f"(d[3])
        : "r"(a[0]), "r"(a[1]), "r"(a[2]), "r"(a[3]),
          "r"(b[0]), "r"(b[1]));
}

// k-group permutation: within each 8-elem group, k -> (k%4)*2 + k/4
// so pairs (k, k+4) become adjacent -> float2 fragment loads.
__device__ __forceinline__ int kperm_(int k) {
    return (k & ~7) + ((k & 3) << 1) + ((k & 7) >> 2);
}

// ================= round to tf32 + k-permute (flat, rows mult of 8) ========
__global__ __launch_bounds__(256)
void round_perm(const float* __restrict__ in, float* __restrict__ out, int n4) {
    int idx = blockIdx.x * 256 + threadIdx.x;
    if (idx >= n4) return;
    float4 v = ((const float4*)in)[idx];
    float vals[4] = { v.x, v.y, v.z, v.w };
    int e = idx * 4;
#pragma unroll
    for (int j = 0; j < 4; ++j)
        out[kperm_(e + j)] = tf32r_(vals[j]);
}

// ======================= rope table: cos/sin per (s,i) =====================
__global__ __launch_bounds__(256)
void rope_table(float2* __restrict__ tab) {
    int idx = blockIdx.x * 256 + threadIdx.x;
    int s = idx >> 6, i = idx & 63;
    float inv_freq = exp2f(-(float)(2 * i) * (1.0f / 128.0f)
                           * 13.28771237954945f);
    float sn, cs;
    sincosf((float)s * inv_freq, &sn, &cs);
    tab[idx] = make_float2(cs, sn);
}

// ===== tf32 mma.sync NT GEMM, cp.async 3-stage, pre-rounded k-perm inputs ==
// 128x128 CTA tile, BK=16, 8 warps (warp tile 32x64), pitch-24 smem
// (pitch 24: float2 frag loads hit 32 distinct banks per LDS.64 phase).
#define GP 24
#define GSTW (128 * GP)
#define GSTAGE (2 * GSTW)
#define GEMM_SMEM (3 * GSTAGE * 4)  // 73728 bytes

__global__ __launch_bounds__(256, 2)
void gemm_tf32mma(const float* __restrict__ A, const float* __restrict__ Bm,
                  float* __restrict__ C, int M, int N, int K) {
    extern __shared__ float smg[];
    const uint32_t sb = smem_u32_(smg);

    const int tid  = threadIdx.x;
    const int lane = tid & 31;
    const int wid  = tid >> 5;
    const int wm   = wid & 3;
    const int wn   = wid >> 2;
    const int m0   = blockIdx.y * 128;
    const int n0   = blockIdx.x * 128;
    const int lg   = lane >> 2;
    const int lq   = lane & 3;

    float acc[2][8][4];
#pragma unroll
    for (int mt = 0; mt < 2; ++mt)
#pragma unroll
        for (int nt = 0; nt < 8; ++nt)
#pragma unroll
            for (int j = 0; j < 4; ++j) acc[mt][nt][j] = 0.f;

    const int row_ld = tid >> 2;
    const int c4_ld  = tid & 3;

    auto ISSUE = [&](int t) {
        const int st = (t % 3);
        const int k0 = t << 4;
        const uint32_t base = sb + (uint32_t)(st * GSTAGE) * 4;
#pragma unroll
        for (int i = 0; i < 2; ++i) {
            int row = row_ld + 64 * i;
            uint32_t off = (uint32_t)(row * GP + 4 * c4_ld) * 4;
            cpa16_(base + off,
                   A + (size_t)(m0 + row) * K + k0 + 4 * c4_ld);
            cpa16_(base + (uint32_t)GSTW * 4 + off,
                   Bm + (size_t)(n0 + row) * K + k0 + 4 * c4_ld);
        }
        CP_COMMIT();
    };

    auto COMPUTE = [&](int t) {
        const float* Sa = smg + (t % 3) * GSTAGE;
        const float* Sb = Sa + GSTW;
#pragma unroll
        for (int ks = 0; ks < 2; ++ks) {
            uint32_t af[2][4], bf[8][2];
#pragma unroll
            for (int mt = 0; mt < 2; ++mt) {
                const float* p = Sa + (wm * 32 + mt * 16 + lg) * GP
                               + ks * 8 + 2 * lq;
                float2 lo = *(const float2*)p;
                float2 hi = *(const float2*)(p + 8 * GP);
                af[mt][0] = __float_as_uint(lo.x);
                af[mt][2] = __float_as_uint(lo.y);
                af[mt][1] = __float_as_uint(hi.x);
                af[mt][3] = __float_as_uint(hi.y);
            }
#pragma unroll
            for (int nt = 0; nt < 8; ++nt) {
                const float* p = Sb + (wn * 64 + nt * 8 + lg) * GP
                               + ks * 8 + 2 * lq;
                float2 v = *(const float2*)p;
                bf[nt][0] = __float_as_uint(v.x);
                bf[nt][1] = __float_as_uint(v.y);
            }
#pragma unroll
            for (int mt = 0; mt < 2; ++mt)
#pragma unroll
                for (int nt = 0; nt < 8; ++nt)
                    mma_tf32_(acc[mt][nt], af[mt], bf[nt]);
        }
    };

    const int ntile = K >> 4;
    ISSUE(0);
    if (ntile > 1) ISSUE(1);
    for (int t = 0; t < ntile; ++t) {
        if (t + 2 < ntile) { ISSUE(t + 2); CP_WAIT2(); }
        else if (t + 1 < ntile) { CP_WAIT1(); }
        else { CP_WAIT0(); }
        __syncthreads();
        COMPUTE(t);
        __syncthreads();
    }

#pragma unroll
    for (int mt = 0; mt < 2; ++mt) {
        int r0 = m0 + wm * 32 + mt * 16 + lg;
#pragma unroll
        for (int nt = 0; nt < 8; ++nt) {
            int c = n0 + wn * 64 + nt * 8 + 2 * lq;
            *(float2*)(C + (size_t)r0 * N + c) =
                make_float2(acc[mt][nt][0], acc[mt][nt][1]);
            *(float2*)(C + (size_t)(r0 + 8) * N + c) =
                make_float2(acc[mt][nt][2], acc[mt][nt][3]);
        }
    }
}

// == RMSNorm + RoPE(table) + transpose; q/k written tf32-rounded + k-perm ===
__global__ __launch_bounds__(256)
void qkv_post(const float* __restrict__ qkv,
              const float* __restrict__ qw, const float* __restrict__ kw,
              const float2* __restrict__ rope,
              float* __restrict__ q_out, float* __restrict__ k_out,
              float* __restrict__ v_out) {
    const int gwarp = blockIdx.x * 8 + (threadIdx.x >> 5);
    const int lane  = threadIdx.x & 31;
    const int h  = gwarp % 24;
    const int bs = gwarp / 24;
    const int s  = bs & (SEQ - 1);
    const int b  = bs >> 11;

    float4 x = *(const float4*)(qkv + (size_t)bs * QKV_OUT + h * HD + 4 * lane);

    if (h < 20) {
        float ss = x.x * x.x + x.y * x.y + x.z * x.z + x.w * x.w;
#pragma unroll
        for (int o = 16; o; o >>= 1) ss += __shfl_xor_sync(~0u, ss, o);
        float rinv = rsqrtf(ss * (1.0f / HD) + 1e-5f);
        const float* wp = (h < 16) ? qw : kw;
        float4 w = *(const float4*)(wp + 4 * lane);
        x.x *= rinv * w.x; x.y *= rinv * w.y;
        x.z *= rinv * w.z; x.w *= rinv * w.w;
        float4 p;
        p.x = __shfl_xor_sync(~0u, x.x, 16);
        p.y = __shfl_xor_sync(~0u, x.y, 16);
        p.z = __shfl_xor_sync(~0u, x.z, 16);
        p.w = __shfl_xor_sync(~0u, x.w, 16);
        const int i0 = 4 * (lane & 15);
        const bool lo = lane < 16;
        float out[4], xv[4] = {x.x, x.y, x.z, x.w}, pv[4] = {p.x, p.y, p.z, p.w};
        const float2* rp = rope + s * 64 + i0;
#pragma unroll
        for (int j = 0; j < 4; ++j) {
            float2 cssn = rp[j];
            float x1 = lo ? xv[j] : pv[j];
            float x2 = lo ? pv[j] : xv[j];
            out[j] = lo ? (x1 * cssn.x - x2 * cssn.y)
                        : (x1 * cssn.y + x2 * cssn.x);
        }
        float* dst = (h < 16)
            ? q_out + (((size_t)b * NH + h) * SEQ + s) * HD
            : k_out + (((size_t)b * NKV + (h - 16)) * SEQ + s) * HD;
#pragma unroll
        for (int j = 0; j < 4; ++j) {
            int d = 4 * lane + j;
            dst[kperm_(d)] = tf32r_(out[j]);
        }
    } else {
        *(float4*)(v_out + (((size_t)b * NKV + (h - 20)) * SEQ + s) * HD + 4 * lane) =
            tf32r4_(x);
    }
}

// ========== gate = sigmoid(x . w_gate[h] + b), w_gate staged in smem =======
#define GATE_SMEM (NH * DMODEL * 4)   // 131072

__global__ __launch_bounds__(256)
void gate_kernel(const float* __restrict__ x, const float* __restrict__ wg,
                 const float* __restrict__ bg, float* __restrict__ gate) {
    extern __shared__ float ws[];
    const int tid = threadIdx.x;
    const int lane = tid & 31;
    const int warp = tid >> 5;
    for (int i = tid; i < NH * DMODEL / 4; i += 256)
        ((float4*)ws)[i] = ((const float4*)wg)[i];
    __syncthreads();

    const int r0 = blockIdx.x * 32;
#pragma unroll 1
    for (int rr = 0; rr < 4; ++rr) {
        const int row = r0 + warp + 8 * rr;
        const float4* xv = (const float4*)(x + (size_t)row * DMODEL);
        float acc[NH];
#pragma unroll
        for (int h = 0; h < NH; ++h) acc[h] = 0.f;
#pragma unroll 4
        for (int it = 0; it < 16; ++it) {
            int i4 = lane + 32 * it;
            float4 a = xv[i4];
#pragma unroll
            for (int h = 0; h < NH; ++h) {
                float4 w = ((const float4*)ws)[h * (DMODEL / 4) + i4];
                acc[h] += a.x * w.x + a.y * w.y + a.z * w.z + a.w * w.w;
            }
        }
#pragma unroll
        for (int h = 0; h < NH; ++h) {
            float v = acc[h];
#pragma unroll
            for (int o = 16; o; o >>= 1) v += __shfl_xor_sync(~0u, v, o);
            if (lane == 0)
                gate[(size_t)row * NH + h] =
                    1.0f / (1.0f + __expf(-(v + bg[h])));
        }
    }
}

// == causal flash attention (tf32 mma, k-perm Q/K float2 frags, cp.async) ===
// CTA: 64 q x 64 kv, 4 warps; 2 CTAs/SM.
#define FBM 64
#define FBN 64
#define FQP 136
#define FKP 136
#define FVP 136
#define FLASH_SMEM ((FBM*FQP + FBN*FKP + FBN*FVP) * 4)   // 104448 B

__global__ __launch_bounds__(128, 2)
void flash_mma(const float* __restrict__ Q, const float* __restrict__ Kt,
               const float* __restrict__ V, const float* __restrict__ gate,
               float* __restrict__ Oout) {
    extern __shared__ float sm[];
    float* Qs = sm;                       // [64][136]  (q, hd k-perm)
    float* Ks = Qs + FBM * FQP;           // [64][136]  (kv, hd k-perm)
    float* Vs = Ks + FBN * FKP;           // [64][136]  (kv, hd natural)
    const uint32_t sQ = smem_u32_(Qs);
    const uint32_t sK = smem_u32_(Ks);
    const uint32_t sV = smem_u32_(Vs);

    const int qt = blockIdx.x;
    const int h  = blockIdx.y;
    const int b  = blockIdx.z;
    const int kvh = h >> 2;
    const int tid = threadIdx.x;
    const int lane = tid & 31;
    const int w = tid >> 5;
    const int lg = lane >> 2;
    const int lq = lane & 3;
    const int q0 = qt * FBM;

    const float* Qg = Q  + (((size_t)b * NH + h) * SEQ + q0) * HD;
    const float* Kg = Kt + ((size_t)b * NKV + kvh) * SEQ * HD;
    const float* Vg = V  + ((size_t)b * NKV + kvh) * SEQ * HD;

    auto ISSUE_KV = [&](int t) {
        const int k0 = t * FBN;
#pragma unroll
        for (int i = 0; i < 16; ++i) {
            int idx = tid + 128 * i;
            int row = idx >> 5, c4 = idx & 31;
            cpa16_(sK + (uint32_t)(row * FKP + 4 * c4) * 4,
                   Kg + (size_t)(k0 + row) * HD + 4 * c4);
        }
#pragma unroll
        for (int i = 0; i < 16; ++i) {
            int idx = tid + 128 * i;
            int row = idx >> 5, c4 = idx & 31;
            cpa16_(sV + (uint32_t)(row * FVP + 4 * c4) * 4,
                   Vg + (size_t)(k0 + row) * HD + 4 * c4);
        }
        CP_COMMIT();
    };

    // prologue: Q + first K/V tile
    {
#pragma unroll
        for (int i = 0; i < 16; ++i) {
            int idx = tid + 128 * i;
            int row = idx >> 5, c4 = idx & 31;
            cpa16_(sQ + (uint32_t)(row * FQP + 4 * c4) * 4,
                   Qg + (size_t)row * HD + 4 * c4);
        }
        CP_COMMIT();
        ISSUE_KV(0);
        CP_WAIT0();
        __syncthreads();
    }

    float mi[2] = { -1e30f, -1e30f }, li[2] = { 0.f, 0.f };
    float o[16][4];
#pragma unroll
    for (int nt = 0; nt < 16; ++nt)
#pragma unroll
        for (int j = 0; j < 4; ++j) o[nt][j] = 0.f;

    const float scl = 0.08838834764831845f;   // 1/sqrt(128)
    const int nkt = qt + 1;

    for (int t = 0; t < nkt; ++t) {
        const int k0 = t * FBN;

        // ---- S = Q K^T (k-perm float2 fragment loads) ----
        float sc[8][4];
#pragma unroll
        for (int nt = 0; nt < 8; ++nt)
#pragma unroll
            for (int j = 0; j < 4; ++j) sc[nt][j] = 0.f;

#pragma unroll
        for (int ks = 0; ks < 16; ++ks) {
            const float* pa = Qs + (16 * w + lg) * FQP + 8 * ks + 2 * lq;
            float2 alo = *(const float2*)pa;
            float2 ahi = *(const float2*)(pa + 8 * FQP);
            uint32_t a[4];
            a[0] = __float_as_uint(alo.x);
            a[2] = __float_as_uint(alo.y);
            a[1] = __float_as_uint(ahi.x);
            a[3] = __float_as_uint(ahi.y);
#pragma unroll
            for (int nt = 0; nt < 8; ++nt) {
                const float* pb = Ks + (8 * nt + lg) * FKP + 8 * ks + 2 * lq;
                float2 bv = *(const float2*)pb;
                uint32_t bf[2];
                bf[0] = __float_as_uint(bv.x);
                bf[1] = __float_as_uint(bv.y);
                mma_tf32_(sc[nt], a, bf);
            }
        }

        // ---- scale + causal mask (only diagonal tile t == qt) ----
        const int qr0 = q0 + 16 * w + lg;
        const int qr1 = qr0 + 8;
        const bool needmask = (t == qt);
#pragma unroll
        for (int nt = 0; nt < 8; ++nt) {
            int c0 = k0 + 8 * nt + 2 * lq, c1 = c0 + 1;
            float s0 = sc[nt][0] * scl, s1 = sc[nt][1] * scl;
            float s2 = sc[nt][2] * scl, s3 = sc[nt][3] * scl;
            if (needmask) {
                if (c0 > qr0) s0 = -1e30f;
                if (c1 > qr0) s1 = -1e30f;
                if (c0 > qr1) s2 = -1e30f;
                if (c1 > qr1) s3 = -1e30f;
            }
            sc[nt][0] = s0; sc[nt][1] = s1; sc[nt][2] = s2; sc[nt][3] = s3;
        }

        // ---- online softmax ----
#pragma unroll
        for (int r = 0; r < 2; ++r) {
            float m = -1e30f;
#pragma unroll
            for (int nt = 0; nt < 8; ++nt)
                m = fmaxf(m, fmaxf(sc[nt][2 * r], sc[nt][2 * r + 1]));
            m = fmaxf(m, __shfl_xor_sync(~0u, m, 1));
            m = fmaxf(m, __shfl_xor_sync(~0u, m, 2));
            float newm = fmaxf(mi[r], m);
            float esc = __expf(mi[r] - newm);
            mi[r] = newm;
            float rs = 0.f;
#pragma unroll
            for (int nt = 0; nt < 8; ++nt) {
                float p0 = __expf(sc[nt][2 * r]     - newm);
                float p1 = __expf(sc[nt][2 * r + 1] - newm);
                sc[nt][2 * r] = p0; sc[nt][2 * r + 1] = p1;
                rs += p0 + p1;
            }
            rs += __shfl_xor_sync(~0u, rs, 1);
            rs += __shfl_xor_sync(~0u, rs, 2);
            li[r] = li[r] * esc + rs;
#pragma unroll
            for (int nt = 0; nt < 16; ++nt) {
                o[nt][2 * r]     *= esc;
                o[nt][2 * r + 1] *= esc;
            }
        }

        // ---- O += P V  (P frags via shuffles; V natural [kv][136]) ----
        const int src0 = (lane & ~3) | (lq >> 1);
        const int src1 = src0 + 2;
        const bool odd = lq & 1;
#pragma unroll
        for (int j = 0; j < 8; ++j) {
            float p00 = __shfl_sync(~0u, sc[j][0], src0);
            float p01 = __shfl_sync(~0u, sc[j][1], src0);
            float p02 = __shfl_sync(~0u, sc[j][2], src0);
            float p03 = __shfl_sync(~0u, sc[j][3], src0);
            float q00 = __shfl_sync(~0u, sc[j][0], src1);
            float q01 = __shfl_sync(~0u, sc[j][1], src1);
            float q02 = __shfl_sync(~0u, sc[j][2], src1);
            float q03 = __shfl_sync(~0u, sc[j][3], src1);
            uint32_t a[4];
            a[0] = __float_as_uint(tf32r_(odd ? p01 : p00));
            a[1] = __float_as_uint(tf32r_(odd ? p03 : p02));
            a[2] = __float_as_uint(tf32r_(odd ? q01 : q00));
            a[3] = __float_as_uint(tf32r_(odd ? q03 : q02));
            const float* pv0 = Vs + (8 * j + lq) * FVP + lg;
#pragma unroll
            for (int nt = 0; nt < 16; ++nt) {
                uint32_t bf[2];
                bf[0] = __float_as_uint(pv0[8 * nt]);
                bf[1] = __float_as_uint(pv0[4 * FVP + 8 * nt]);
                mma_tf32_(o[nt], a, bf);
            }
        }

        if (t + 1 < nkt) {
            __syncthreads();
            ISSUE_KV(t + 1);
            CP_WAIT0();
            __syncthreads();
        }
    }

    // ---- epilogue: /li, *gate, tf32-round + k-perm scatter to attn ----
#pragma unroll
    for (int r = 0; r < 2; ++r) {
        int row = q0 + 16 * w + lg + 8 * r;
        float g = gate[((size_t)b * SEQ + row) * NH + h];
        float inv = g / li[r];
        float* dst = Oout + ((size_t)(b * SEQ + row)) * (NH * HD) + h * HD;
#pragma unroll
        for (int nt = 0; nt < 16; ++nt) {
            int k0e = 2 * lq, k1e = 2 * lq + 1;
            int c0 = 8 * nt + ((k0e & 3) << 1) + (k0e >> 2);
            int c1 = 8 * nt + ((k1e & 3) << 1) + (k1e >> 2);
            dst[c0] = tf32r_(o[nt][2 * r] * inv);
            dst[c1] = tf32r_(o[nt][2 * r + 1] * inv);
        }
    }
}

// ================================ launch ===================================
extern "C" void kernel_launch(void* const* d_in, const int* in_sizes, int n_in,
                              void* d_out, int out_size) {
    const float* x      = (const float*)d_in[0];
    const float* w_qkv  = (const float*)d_in[1];
    const float* qnw    = (const float*)d_in[2];
    const float* knw    = (const float*)d_in[3];
    const float* w_gate = (const float*)d_in[4];
    const float* b_gate = (const float*)d_in[5];
    const float* w_o    = (const float*)d_in[6];
    float* out = (float*)d_out;

    float *qkv, *q, *k, *v, *gate, *attn, *xr, *wqkvr, *wor;
    float2* rope;
    cudaGetSymbolAddress((void**)&qkv,   g_qkv);
    cudaGetSymbolAddress((void**)&q,     g_q);
    cudaGetSymbolAddress((void**)&k,     g_k);
    cudaGetSymbolAddress((void**)&v,     g_v);
    cudaGetSymbolAddress((void**)&gate,  g_gate);
    cudaGetSymbolAddress((void**)&attn,  g_attn);
    cudaGetSymbolAddress((void**)&rope,  g_rope);
    cudaGetSymbolAddress((void**)&xr,    g_xr);
    cudaGetSymbolAddress((void**)&wqkvr, g_wqkvr);
    cudaGetSymbolAddress((void**)&wor,   g_wor);

    cudaFuncSetAttribute(gemm_tf32mma,
                         cudaFuncAttributeMaxDynamicSharedMemorySize, GEMM_SMEM);
    cudaFuncSetAttribute(flash_mma,
                         cudaFuncAttributeMaxDynamicSharedMemorySize, FLASH_SMEM);
    cudaFuncSetAttribute(gate_kernel,
                         cudaFuncAttributeMaxDynamicSharedMemorySize, GATE_SMEM);

    // 0) prep: rope table + tf32-round/k-permute GEMM operands
    rope_table<<<SEQ * 64 / 256, 256>>>(rope);
    round_perm<<<(BSTOT * DMODEL / 4) / 256, 256>>>(x, xr, BSTOT * DMODEL / 4);
    round_perm<<<(QKV_OUT * DMODEL / 4) / 256, 256>>>(w_qkv, wqkvr,
                                                      QKV_OUT * DMODEL / 4);
    round_perm<<<(DMODEL * DMODEL / 4) / 256, 256>>>(w_o, wor,
                                                     DMODEL * DMODEL / 4);
    // 1) QKV projection: [4096,2048] x [3072,2048]^T (pre-rounded, k-perm)
    {
        dim3 grid(QKV_OUT / 128, BSTOT / 128);
        gemm_tf32mma<<<grid, 256, GEMM_SMEM>>>(xr, wqkvr, qkv,
                                               BSTOT, QKV_OUT, DMODEL);
    }
    // 2) RMSNorm + RoPE(table) + layout (q/k tf32-rounded + k-perm)
    {
        qkv_post<<<(BSTOT * 24) / 8, 256>>>(qkv, qnw, knw, rope, q, k, v);
    }
    // 3) gate (w_gate staged in smem; reads original x)
    {
        gate_kernel<<<BSTOT / 32, 256, GATE_SMEM>>>(x, w_gate, b_gate, gate);
    }
    // 4) flash attention, tf32 mma (gated epilogue, writes rounded+perm attn)
    {
        dim3 grid(SEQ / FBM, NH, BATCH);
        flash_mma<<<grid, 128, FLASH_SMEM>>>(q, k, v, gate, attn);
    }
    // 5) output projection: [4096,2048] x [2048,2048]^T -> d_out
    {
        dim3 grid(DMODEL / 128, BSTOT / 128);
        gemm_tf32mma<<<grid, 256, GEMM_SMEM>>>(attn, wor, out,
                                               BSTOT, DMODEL, DMODEL);
    }
}

// round 15
// speedup vs baseline: 1.1892x; 1.0335x over previous
#include <cuda_runtime.h>
#include <cuda_bf16.h>
#include <math.h>
#include <cstdint>

#define BATCH 2
#define SEQ 2048
#define DMODEL 2048
#define NH 16
#define NKV 4
#define HD 128
#define NREP 4
#define QKV_OUT 3072   // (16 + 2*4) * 128
#define BSTOT (BATCH*SEQ)

// ---------------- scratch (device globals; no allocation allowed) ----------
__device__ float g_qkv  [BSTOT * QKV_OUT];        // 48 MB
__device__ float g_q    [BATCH * NH  * SEQ * HD]; // 32 MB (tf32, k-perm)
__device__ float g_k    [BATCH * NKV * SEQ * HD]; //  8 MB (tf32, k-perm)
__device__ float g_v    [BATCH * NKV * SEQ * HD]; //  8 MB (tf32)
__device__ float g_gate [BSTOT * NH];             // 0.5 MB
__device__ float g_attn [BSTOT * (NH*HD)];        // 32 MB (tf32, k-perm)
__device__ float2 g_rope[SEQ * 64];               // 1 MB
__device__ float g_xr   [BSTOT * DMODEL];         // 32 MB (x, tf32, k-perm)
__device__ float g_wqkvr[QKV_OUT * DMODEL];       // 24 MB (w_qkv, tf32, k-perm)
__device__ float g_wor  [DMODEL * DMODEL];        // 16 MB (w_o, tf32, k-perm)

// ========================== helpers ========================================
__device__ __forceinline__ float tf32r_(float x) {
    uint32_t r;
    asm("cvt.rna.tf32.f32 %0, %1;" : "=r"(r) : "f"(x));
    return __uint_as_float(r);
}
__device__ __forceinline__ float4 tf32r4_(float4 v) {
    v.x = tf32r_(v.x); v.y = tf32r_(v.y);
    v.z = tf32r_(v.z); v.w = tf32r_(v.w);
    return v;
}
__device__ __forceinline__ uint32_t smem_u32_(const void* p) {
    uint32_t a;
    asm("{ .reg .u64 t; cvta.to.shared.u64 t, %1; cvt.u32.u64 %0, t; }"
        : "=r"(a) : "l"(p));
    return a;
}
__device__ __forceinline__ void cpa16_(uint32_t dst, const void* src) {
    asm volatile("cp.async.cg.shared.global [%0], [%1], 16;"
                 :: "r"(dst), "l"(src));
}
#define CP_COMMIT() asm volatile("cp.async.commit_group;" ::: "memory")
#define CP_WAIT0()  asm volatile("cp.async.wait_group 0;" ::: "memory")
#define CP_WAIT1()  asm volatile("cp.async.wait_group 1;" ::: "memory")
#define CP_WAIT2()  asm volatile("cp.async.wait_group 2;" ::: "memory")

// D += A(16x8,row) * B(8x8,col)  tf32 inputs, f32 accum
__device__ __forceinline__ void mma_tf32_(float* d, const uint32_t* a,
                                          const uint32_t* b) {
    asm volatile(
        "mma.sync.aligned.m16n8k8.row.col.f32.tf32.tf32.f32 "
        "{%0,%1,%2,%3}, {%4,%5,%6,%7}, {%8,%9}, {%0,%1,%2,%3};\n"
        : "+f"(d[0]), "+f"(d[1]), "+f"(d[2]), "+f"(d[3])
        : "r"(a[0]), "r"(a[1]), "r"(a[2]), "r"(a[3]),
          "r"(b[0]), "r"(b[1]));
}

// k-group permutation: within each 8-elem group, k -> (k%4)*2 + k/4
// so pairs (k, k+4) become adjacent -> float2 fragment loads.
__device__ __forceinline__ int kperm_(int k) {
    return (k & ~7) + ((k & 3) << 1) + ((k & 7) >> 2);
}

// ================= round to tf32 + k-permute (flat, rows mult of 8) ========
__global__ __launch_bounds__(256)
void round_perm(const float* __restrict__ in, float* __restrict__ out, int n4) {
    int idx = blockIdx.x * 256 + threadIdx.x;
    if (idx >= n4) return;
    float4 v = ((const float4*)in)[idx];
    float vals[4] = { v.x, v.y, v.z, v.w };
    int e = idx * 4;
#pragma unroll
    for (int j = 0; j < 4; ++j)
        out[kperm_(e + j)] = tf32r_(vals[j]);
}

// ======================= rope table: cos/sin per (s,i) =====================
__global__ __launch_bounds__(256)
void rope_table(float2* __restrict__ tab) {
    int idx = blockIdx.x * 256 + threadIdx.x;
    int s = idx >> 6, i = idx & 63;
    float inv_freq = exp2f(-(float)(2 * i) * (1.0f / 128.0f)
                           * 13.28771237954945f);
    float sn, cs;
    sincosf((float)s * inv_freq, &sn, &cs);
    tab[idx] = make_float2(cs, sn);
}

// ===== tf32 mma.sync NT GEMM, cp.async 4-stage, ONE sync/tile ==============
// 128x128 CTA tile, BK=16, 8 warps (warp tile 32x64), pitch-24 smem.
// Loop order WAIT -> sync -> ISSUE -> COMPUTE: the single barrier both
// publishes the awaited stage and guarantees stage (t-1)%4 is free.
#define GP 24
#define GSTW (128 * GP)
#define GSTAGE (2 * GSTW)
#define GNSTG 4
#define GEMM_SMEM (GNSTG * GSTAGE * 4)  // 98304 bytes

__global__ __launch_bounds__(256, 2)
void gemm_tf32mma(const float* __restrict__ A, const float* __restrict__ Bm,
                  float* __restrict__ C, int M, int N, int K) {
    extern __shared__ float smg[];
    const uint32_t sb = smem_u32_(smg);

    const int tid  = threadIdx.x;
    const int lane = tid & 31;
    const int wid  = tid >> 5;
    const int wm   = wid & 3;
    const int wn   = wid >> 2;
    const int m0   = blockIdx.y * 128;
    const int n0   = blockIdx.x * 128;
    const int lg   = lane >> 2;
    const int lq   = lane & 3;

    float acc[2][8][4];
#pragma unroll
    for (int mt = 0; mt < 2; ++mt)
#pragma unroll
        for (int nt = 0; nt < 8; ++nt)
#pragma unroll
            for (int j = 0; j < 4; ++j) acc[mt][nt][j] = 0.f;

    const int row_ld = tid >> 2;
    const int c4_ld  = tid & 3;

    auto ISSUE = [&](int t) {
        const int st = (t & (GNSTG - 1));
        const int k0 = t << 4;
        const uint32_t base = sb + (uint32_t)(st * GSTAGE) * 4;
#pragma unroll
        for (int i = 0; i < 2; ++i) {
            int row = row_ld + 64 * i;
            uint32_t off = (uint32_t)(row * GP + 4 * c4_ld) * 4;
            cpa16_(base + off,
                   A + (size_t)(m0 + row) * K + k0 + 4 * c4_ld);
            cpa16_(base + (uint32_t)GSTW * 4 + off,
                   Bm + (size_t)(n0 + row) * K + k0 + 4 * c4_ld);
        }
        CP_COMMIT();
    };

    auto COMPUTE = [&](int t) {
        const float* Sa = smg + (t & (GNSTG - 1)) * GSTAGE;
        const float* Sb = Sa + GSTW;
#pragma unroll
        for (int ks = 0; ks < 2; ++ks) {
            uint32_t af[2][4], bf[8][2];
#pragma unroll
            for (int mt = 0; mt < 2; ++mt) {
                const float* p = Sa + (wm * 32 + mt * 16 + lg) * GP
                               + ks * 8 + 2 * lq;
                float2 lo = *(const float2*)p;
                float2 hi = *(const float2*)(p + 8 * GP);
                af[mt][0] = __float_as_uint(lo.x);
                af[mt][2] = __float_as_uint(lo.y);
                af[mt][1] = __float_as_uint(hi.x);
                af[mt][3] = __float_as_uint(hi.y);
            }
#pragma unroll
            for (int nt = 0; nt < 8; ++nt) {
                const float* p = Sb + (wn * 64 + nt * 8 + lg) * GP
                               + ks * 8 + 2 * lq;
                float2 v = *(const float2*)p;
                bf[nt][0] = __float_as_uint(v.x);
                bf[nt][1] = __float_as_uint(v.y);
            }
#pragma unroll
            for (int mt = 0; mt < 2; ++mt)
#pragma unroll
                for (int nt = 0; nt < 8; ++nt)
                    mma_tf32_(acc[mt][nt], af[mt], bf[nt]);
        }
    };

    const int ntile = K >> 4;
    ISSUE(0);
    ISSUE(1);
    ISSUE(2);
    for (int t = 0; t < ntile; ++t) {
        const int rem = ntile - 1 - t;
        if (rem >= 2)      { CP_WAIT2(); }
        else if (rem == 1) { CP_WAIT1(); }
        else               { CP_WAIT0(); }
        __syncthreads();
        if (t + 3 < ntile) ISSUE(t + 3);
        COMPUTE(t);
    }

#pragma unroll
    for (int mt = 0; mt < 2; ++mt) {
        int r0 = m0 + wm * 32 + mt * 16 + lg;
#pragma unroll
        for (int nt = 0; nt < 8; ++nt) {
            int c = n0 + wn * 64 + nt * 8 + 2 * lq;
            *(float2*)(C + (size_t)r0 * N + c) =
                make_float2(acc[mt][nt][0], acc[mt][nt][1]);
            *(float2*)(C + (size_t)(r0 + 8) * N + c) =
                make_float2(acc[mt][nt][2], acc[mt][nt][3]);
        }
    }
}

// == RMSNorm + RoPE(table) + transpose; q/k written tf32-rounded + k-perm ===
__global__ __launch_bounds__(256)
void qkv_post(const float* __restrict__ qkv,
              const float* __restrict__ qw, const float* __restrict__ kw,
              const float2* __restrict__ rope,
              float* __restrict__ q_out, float* __restrict__ k_out,
              float* __restrict__ v_out) {
    const int gwarp = blockIdx.x * 8 + (threadIdx.x >> 5);
    const int lane  = threadIdx.x & 31;
    const int h  = gwarp % 24;
    const int bs = gwarp / 24;
    const int s  = bs & (SEQ - 1);
    const int b  = bs >> 11;

    float4 x = *(const float4*)(qkv + (size_t)bs * QKV_OUT + h * HD + 4 * lane);

    if (h < 20) {
        float ss = x.x * x.x + x.y * x.y + x.z * x.z + x.w * x.w;
#pragma unroll
        for (int o = 16; o; o >>= 1) ss += __shfl_xor_sync(~0u, ss, o);
        float rinv = rsqrtf(ss * (1.0f / HD) + 1e-5f);
        const float* wp = (h < 16) ? qw : kw;
        float4 w = *(const float4*)(wp + 4 * lane);
        x.x *= rinv * w.x; x.y *= rinv * w.y;
        x.z *= rinv * w.z; x.w *= rinv * w.w;
        float4 p;
        p.x = __shfl_xor_sync(~0u, x.x, 16);
        p.y = __shfl_xor_sync(~0u, x.y, 16);
        p.z = __shfl_xor_sync(~0u, x.z, 16);
        p.w = __shfl_xor_sync(~0u, x.w, 16);
        const int i0 = 4 * (lane & 15);
        const bool lo = lane < 16;
        float out[4], xv[4] = {x.x, x.y, x.z, x.w}, pv[4] = {p.x, p.y, p.z, p.w};
        const float2* rp = rope + s * 64 + i0;
#pragma unroll
        for (int j = 0; j < 4; ++j) {
            float2 cssn = rp[j];
            float x1 = lo ? xv[j] : pv[j];
            float x2 = lo ? pv[j] : xv[j];
            out[j] = lo ? (x1 * cssn.x - x2 * cssn.y)
                        : (x1 * cssn.y + x2 * cssn.x);
        }
        float* dst = (h < 16)
            ? q_out + (((size_t)b * NH + h) * SEQ + s) * HD
            : k_out + (((size_t)b * NKV + (h - 16)) * SEQ + s) * HD;
#pragma unroll
        for (int j = 0; j < 4; ++j) {
            int d = 4 * lane + j;
            dst[kperm_(d)] = tf32r_(out[j]);
        }
    } else {
        *(float4*)(v_out + (((size_t)b * NKV + (h - 20)) * SEQ + s) * HD + 4 * lane) =
            tf32r4_(x);
    }
}

// ========== gate = sigmoid(x . w_gate[h] + b), w_gate staged in smem =======
#define GATE_SMEM (NH * DMODEL * 4)   // 131072

__global__ __launch_bounds__(256)
void gate_kernel(const float* __restrict__ x, const float* __restrict__ wg,
                 const float* __restrict__ bg, float* __restrict__ gate) {
    extern __shared__ float ws[];
    const int tid = threadIdx.x;
    const int lane = tid & 31;
    const int warp = tid >> 5;
    for (int i = tid; i < NH * DMODEL / 4; i += 256)
        ((float4*)ws)[i] = ((const float4*)wg)[i];
    __syncthreads();

    const int r0 = blockIdx.x * 32;
#pragma unroll 1
    for (int rr = 0; rr < 4; ++rr) {
        const int row = r0 + warp + 8 * rr;
        const float4* xv = (const float4*)(x + (size_t)row * DMODEL);
        float acc[NH];
#pragma unroll
        for (int h = 0; h < NH; ++h) acc[h] = 0.f;
#pragma unroll 4
        for (int it = 0; it < 16; ++it) {
            int i4 = lane + 32 * it;
            float4 a = xv[i4];
#pragma unroll
            for (int h = 0; h < NH; ++h) {
                float4 w = ((const float4*)ws)[h * (DMODEL / 4) + i4];
                acc[h] += a.x * w.x + a.y * w.y + a.z * w.z + a.w * w.w;
            }
        }
#pragma unroll
        for (int h = 0; h < NH; ++h) {
            float v = acc[h];
#pragma unroll
            for (int o = 16; o; o >>= 1) v += __shfl_xor_sync(~0u, v, o);
            if (lane == 0)
                gate[(size_t)row * NH + h] =
                    1.0f / (1.0f + __expf(-(v + bg[h])));
        }
    }
}

// == causal flash attention (tf32 mma, k-perm Q/K float2 frags, cp.async) ===
// CTA: 64 q x 64 kv, 4 warps; 2 CTAs/SM.
#define FBM 64
#define FBN 64
#define FQP 136
#define FKP 136
#define FVP 136
#define FLASH_SMEM ((FBM*FQP + FBN*FKP + FBN*FVP) * 4)   // 104448 B

__global__ __launch_bounds__(128, 2)
void flash_mma(const float* __restrict__ Q, const float* __restrict__ Kt,
               const float* __restrict__ V, const float* __restrict__ gate,
               float* __restrict__ Oout) {
    extern __shared__ float sm[];
    float* Qs = sm;                       // [64][136]  (q, hd k-perm)
    float* Ks = Qs + FBM * FQP;           // [64][136]  (kv, hd k-perm)
    float* Vs = Ks + FBN * FKP;           // [64][136]  (kv, hd natural)
    const uint32_t sQ = smem_u32_(Qs);
    const uint32_t sK = smem_u32_(Ks);
    const uint32_t sV = smem_u32_(Vs);

    const int qt = blockIdx.x;
    const int h  = blockIdx.y;
    const int b  = blockIdx.z;
    const int kvh = h >> 2;
    const int tid = threadIdx.x;
    const int lane = tid & 31;
    const int w = tid >> 5;
    const int lg = lane >> 2;
    const int lq = lane & 3;
    const int q0 = qt * FBM;

    const float* Qg = Q  + (((size_t)b * NH + h) * SEQ + q0) * HD;
    const float* Kg = Kt + ((size_t)b * NKV + kvh) * SEQ * HD;
    const float* Vg = V  + ((size_t)b * NKV + kvh) * SEQ * HD;

    auto ISSUE_KV = [&](int t) {
        const int k0 = t * FBN;
#pragma unroll
        for (int i = 0; i < 16; ++i) {
            int idx = tid + 128 * i;
            int row = idx >> 5, c4 = idx & 31;
            cpa16_(sK + (uint32_t)(row * FKP + 4 * c4) * 4,
                   Kg + (size_t)(k0 + row) * HD + 4 * c4);
        }
#pragma unroll
        for (int i = 0; i < 16; ++i) {
            int idx = tid + 128 * i;
            int row = idx >> 5, c4 = idx & 31;
            cpa16_(sV + (uint32_t)(row * FVP + 4 * c4) * 4,
                   Vg + (size_t)(k0 + row) * HD + 4 * c4);
        }
        CP_COMMIT();
    };

    // prologue: Q + first K/V tile
    {
#pragma unroll
        for (int i = 0; i < 16; ++i) {
            int idx = tid + 128 * i;
            int row = idx >> 5, c4 = idx & 31;
            cpa16_(sQ + (uint32_t)(row * FQP + 4 * c4) * 4,
                   Qg + (size_t)row * HD + 4 * c4);
        }
        CP_COMMIT();
        ISSUE_KV(0);
        CP_WAIT0();
        __syncthreads();
    }

    float mi[2] = { -1e30f, -1e30f }, li[2] = { 0.f, 0.f };
    float o[16][4];
#pragma unroll
    for (int nt = 0; nt < 16; ++nt)
#pragma unroll
        for (int j = 0; j < 4; ++j) o[nt][j] = 0.f;

    const float scl = 0.08838834764831845f;   // 1/sqrt(128)
    const int nkt = qt + 1;

    for (int t = 0; t < nkt; ++t) {
        const int k0 = t * FBN;

        // ---- S = Q K^T (k-perm float2 fragment loads) ----
        float sc[8][4];
#pragma unroll
        for (int nt = 0; nt < 8; ++nt)
#pragma unroll
            for (int j = 0; j < 4; ++j) sc[nt][j] = 0.f;

#pragma unroll
        for (int ks = 0; ks < 16; ++ks) {
            const float* pa = Qs + (16 * w + lg) * FQP + 8 * ks + 2 * lq;
            float2 alo = *(const float2*)pa;
            float2 ahi = *(const float2*)(pa + 8 * FQP);
            uint32_t a[4];
            a[0] = __float_as_uint(alo.x);
            a[2] = __float_as_uint(alo.y);
            a[1] = __float_as_uint(ahi.x);
            a[3] = __float_as_uint(ahi.y);
#pragma unroll
            for (int nt = 0; nt < 8; ++nt) {
                const float* pb = Ks + (8 * nt + lg) * FKP + 8 * ks + 2 * lq;
                float2 bv = *(const float2*)pb;
                uint32_t bf[2];
                bf[0] = __float_as_uint(bv.x);
                bf[1] = __float_as_uint(bv.y);
                mma_tf32_(sc[nt], a, bf);
            }
        }

        // ---- scale + causal mask (only diagonal tile t == qt) ----
        const int qr0 = q0 + 16 * w + lg;
        const int qr1 = qr0 + 8;
        const bool needmask = (t == qt);
#pragma unroll
        for (int nt = 0; nt < 8; ++nt) {
            int c0 = k0 + 8 * nt + 2 * lq, c1 = c0 + 1;
            float s0 = sc[nt][0] * scl, s1 = sc[nt][1] * scl;
            float s2 = sc[nt][2] * scl, s3 = sc[nt][3] * scl;
            if (needmask) {
                if (c0 > qr0) s0 = -1e30f;
                if (c1 > qr0) s1 = -1e30f;
                if (c0 > qr1) s2 = -1e30f;
                if (c1 > qr1) s3 = -1e30f;
            }
            sc[nt][0] = s0; sc[nt][1] = s1; sc[nt][2] = s2; sc[nt][3] = s3;
        }

        // ---- online softmax ----
#pragma unroll
        for (int r = 0; r < 2; ++r) {
            float m = -1e30f;
#pragma unroll
            for (int nt = 0; nt < 8; ++nt)
                m = fmaxf(m, fmaxf(sc[nt][2 * r], sc[nt][2 * r + 1]));
            m = fmaxf(m, __shfl_xor_sync(~0u, m, 1));
            m = fmaxf(m, __shfl_xor_sync(~0u, m, 2));
            float newm = fmaxf(mi[r], m);
            float esc = __expf(mi[r] - newm);
            mi[r] = newm;
            float rs = 0.f;
#pragma unroll
            for (int nt = 0; nt < 8; ++nt) {
                float p0 = __expf(sc[nt][2 * r]     - newm);
                float p1 = __expf(sc[nt][2 * r + 1] - newm);
                sc[nt][2 * r] = p0; sc[nt][2 * r + 1] = p1;
                rs += p0 + p1;
            }
            rs += __shfl_xor_sync(~0u, rs, 1);
            rs += __shfl_xor_sync(~0u, rs, 2);
            li[r] = li[r] * esc + rs;
#pragma unroll
            for (int nt = 0; nt < 16; ++nt) {
                o[nt][2 * r]     *= esc;
                o[nt][2 * r + 1] *= esc;
            }
        }

        // ---- O += P V  (P frags via shuffles; V natural [kv][136]) ----
        const int src0 = (lane & ~3) | (lq >> 1);
        const int src1 = src0 + 2;
        const bool odd = lq & 1;
#pragma unroll
        for (int j = 0; j < 8; ++j) {
            float p00 = __shfl_sync(~0u, sc[j][0], src0);
            float p01 = __shfl_sync(~0u, sc[j][1], src0);
            float p02 = __shfl_sync(~0u, sc[j][2], src0);
            float p03 = __shfl_sync(~0u, sc[j][3], src0);
            float q00 = __shfl_sync(~0u, sc[j][0], src1);
            float q01 = __shfl_sync(~0u, sc[j][1], src1);
            float q02 = __shfl_sync(~0u, sc[j][2], src1);
            float q03 = __shfl_sync(~0u, sc[j][3], src1);
            uint32_t a[4];
            a[0] = __float_as_uint(tf32r_(odd ? p01 : p00));
            a[1] = __float_as_uint(tf32r_(odd ? p03 : p02));
            a[2] = __float_as_uint(tf32r_(odd ? q01 : q00));
            a[3] = __float_as_uint(tf32r_(odd ? q03 : q02));
            const float* pv0 = Vs + (8 * j + lq) * FVP + lg;
#pragma unroll
            for (int nt = 0; nt < 16; ++nt) {
                uint32_t bf[2];
                bf[0] = __float_as_uint(pv0[8 * nt]);
                bf[1] = __float_as_uint(pv0[4 * FVP + 8 * nt]);
                mma_tf32_(o[nt], a, bf);
            }
        }

        if (t + 1 < nkt) {
            __syncthreads();
            ISSUE_KV(t + 1);
            CP_WAIT0();
            __syncthreads();
        }
    }

    // ---- epilogue: /li, *gate, tf32-round + k-perm scatter to attn ----
#pragma unroll
    for (int r = 0; r < 2; ++r) {
        int row = q0 + 16 * w + lg + 8 * r;
        float g = gate[((size_t)b * SEQ + row) * NH + h];
        float inv = g / li[r];
        float* dst = Oout + ((size_t)(b * SEQ + row)) * (NH * HD) + h * HD;
#pragma unroll
        for (int nt = 0; nt < 16; ++nt) {
            int k0e = 2 * lq, k1e = 2 * lq + 1;
            int c0 = 8 * nt + ((k0e & 3) << 1) + (k0e >> 2);
            int c1 = 8 * nt + ((k1e & 3) << 1) + (k1e >> 2);
            dst[c0] = tf32r_(o[nt][2 * r] * inv);
            dst[c1] = tf32r_(o[nt][2 * r + 1] * inv);
        }
    }
}

// ================================ launch ===================================
extern "C" void kernel_launch(void* const* d_in, const int* in_sizes, int n_in,
                              void* d_out, int out_size) {
    const float* x      = (const float*)d_in[0];
    const float* w_qkv  = (const float*)d_in[1];
    const float* qnw    = (const float*)d_in[2];
    const float* knw    = (const float*)d_in[3];
    const float* w_gate = (const float*)d_in[4];
    const float* b_gate = (const float*)d_in[5];
    const float* w_o    = (const float*)d_in[6];
    float* out = (float*)d_out;

    float *qkv, *q, *k, *v, *gate, *attn, *xr, *wqkvr, *wor;
    float2* rope;
    cudaGetSymbolAddress((void**)&qkv,   g_qkv);
    cudaGetSymbolAddress((void**)&q,     g_q);
    cudaGetSymbolAddress((void**)&k,     g_k);
    cudaGetSymbolAddress((void**)&v,     g_v);
    cudaGetSymbolAddress((void**)&gate,  g_gate);
    cudaGetSymbolAddress((void**)&attn,  g_attn);
    cudaGetSymbolAddress((void**)&rope,  g_rope);
    cudaGetSymbolAddress((void**)&xr,    g_xr);
    cudaGetSymbolAddress((void**)&wqkvr, g_wqkvr);
    cudaGetSymbolAddress((void**)&wor,   g_wor);

    cudaFuncSetAttribute(gemm_tf32mma,
                         cudaFuncAttributeMaxDynamicSharedMemorySize, GEMM_SMEM);
    cudaFuncSetAttribute(flash_mma,
                         cudaFuncAttributeMaxDynamicSharedMemorySize, FLASH_SMEM);
    cudaFuncSetAttribute(gate_kernel,
                         cudaFuncAttributeMaxDynamicSharedMemorySize, GATE_SMEM);

    // 0) prep: rope table + tf32-round/k-permute GEMM operands
    rope_table<<<SEQ * 64 / 256, 256>>>(rope);
    round_perm<<<(BSTOT * DMODEL / 4) / 256, 256>>>(x, xr, BSTOT * DMODEL / 4);
    round_perm<<<(QKV_OUT * DMODEL / 4) / 256, 256>>>(w_qkv, wqkvr,
                                                      QKV_OUT * DMODEL / 4);
    round_perm<<<(DMODEL * DMODEL / 4) / 256, 256>>>(w_o, wor,
                                                     DMODEL * DMODEL / 4);
    // 1) QKV projection: [4096,2048] x [3072,2048]^T (pre-rounded, k-perm)
    {
        dim3 grid(QKV_OUT / 128, BSTOT / 128);
        gemm_tf32mma<<<grid, 256, GEMM_SMEM>>>(xr, wqkvr, qkv,
                                               BSTOT, QKV_OUT, DMODEL);
    }
    // 2) RMSNorm + RoPE(table) + layout (q/k tf32-rounded + k-perm)
    {
        qkv_post<<<(BSTOT * 24) / 8, 256>>>(qkv, qnw, knw, rope, q, k, v);
    }
    // 3) gate (w_gate staged in smem; reads original x)
    {
        gate_kernel<<<BSTOT / 32, 256, GATE_SMEM>>>(x, w_gate, b_gate, gate);
    }
    // 4) flash attention, tf32 mma (gated epilogue, writes rounded+perm attn)
    {
        dim3 grid(SEQ / FBM, NH, BATCH);
        flash_mma<<<grid, 128, FLASH_SMEM>>>(q, k, v, gate, attn);
    }
    // 5) output projection: [4096,2048] x [2048,2048]^T -> d_out
    {
        dim3 grid(DMODEL / 128, BSTOT / 128);
        gemm_tf32mma<<<grid, 256, GEMM_SMEM>>>(attn, wor, out,
                                               BSTOT, DMODEL, DMODEL);
    }
}

// round 16
// speedup vs baseline: 1.6917x; 1.4226x over previous
#include <cuda_runtime.h>
#include <cuda_fp16.h>
#include <cuda_bf16.h>
#include <math.h>
#include <cstdint>

#define BATCH 2
#define SEQ 2048
#define DMODEL 2048
#define NH 16
#define NKV 4
#define HD 128
#define NREP 4
#define QKV_OUT 3072   // (16 + 2*4) * 128
#define BSTOT (BATCH*SEQ)

// ---------------- scratch (device globals; no allocation allowed) ----------
__device__ float  g_qkv  [BSTOT * QKV_OUT];        // 48 MB
__device__ float  g_q    [BATCH * NH  * SEQ * HD]; // 32 MB (tf32, k8-perm)
__device__ float  g_k    [BATCH * NKV * SEQ * HD]; //  8 MB (tf32, k8-perm)
__device__ float  g_v    [BATCH * NKV * SEQ * HD]; //  8 MB (tf32)
__device__ float  g_gate [BSTOT * NH];             // 0.5 MB
__device__ __half g_attnh[BSTOT * (NH*HD)];        // 16 MB (fp16, k16-perm)
__device__ float2 g_rope [SEQ * 64];               // 1 MB
__device__ __half g_xh   [BSTOT * DMODEL];         // 16 MB (fp16, k16-perm)
__device__ __half g_wqkvh[QKV_OUT * DMODEL];       // 12 MB (fp16, k16-perm)
__device__ __half g_woh  [DMODEL * DMODEL];        //  8 MB (fp16, k16-perm)

// ========================== helpers ========================================
__device__ __forceinline__ float tf32r_(float x) {
    uint32_t r;
    asm("cvt.rna.tf32.f32 %0, %1;" : "=r"(r) : "f"(x));
    return __uint_as_float(r);
}
__device__ __forceinline__ float4 tf32r4_(float4 v) {
    v.x = tf32r_(v.x); v.y = tf32r_(v.y);
    v.z = tf32r_(v.z); v.w = tf32r_(v.w);
    return v;
}
__device__ __forceinline__ uint32_t smem_u32_(const void* p) {
    uint32_t a;
    asm("{ .reg .u64 t; cvta.to.shared.u64 t, %1; cvt.u32.u64 %0, t; }"
        : "=r"(a) : "l"(p));
    return a;
}
__device__ __forceinline__ void cpa16_(uint32_t dst, const void* src) {
    asm volatile("cp.async.cg.shared.global [%0], [%1], 16;"
                 :: "r"(dst), "l"(src));
}
#define CP_COMMIT() asm volatile("cp.async.commit_group;" ::: "memory")
#define CP_WAIT0()  asm volatile("cp.async.wait_group 0;" ::: "memory")
#define CP_WAIT1()  asm volatile("cp.async.wait_group 1;" ::: "memory")
#define CP_WAIT2()  asm volatile("cp.async.wait_group 2;" ::: "memory")

// tf32: D += A(16x8,row) * B(8x8,col)
__device__ __forceinline__ void mma_tf32_(float* d, const uint32_t* a,
                                          const uint32_t* b) {
    asm volatile(
        "mma.sync.aligned.m16n8k8.row.col.f32.tf32.tf32.f32 "
        "{%0,%1,%2,%3}, {%4,%5,%6,%7}, {%8,%9}, {%0,%1,%2,%3};\n"
        : "+f"(d[0]), "+f"(d[1]), "+f"(d[2]), "+f"(d[3])
        : "r"(a[0]), "r"(a[1]), "r"(a[2]), "r"(a[3]),
          "r"(b[0]), "r"(b[1]));
}
// fp16: D(f32) += A(16x16,row,f16) * B(16x8,col,f16)
__device__ __forceinline__ void mma_f16_(float* d, const uint32_t* a,
                                         const uint32_t* b) {
    asm volatile(
        "mma.sync.aligned.m16n8k16.row.col.f32.f16.f16.f32 "
        "{%0,%1,%2,%3}, {%4,%5,%6,%7}, {%8,%9}, {%0,%1,%2,%3};\n"
        : "+f"(d[0]), "+f"(d[1]), "+f"(d[2]), "+f"(d[3])
        : "r"(a[0]), "r"(a[1]), "r"(a[2]), "r"(a[3]),
          "r"(b[0]), "r"(b[1]));
}

// k8-perm (tf32 path, flash): within 8-group, k -> (k%4)*2 + k/4
__device__ __forceinline__ int kperm_(int k) {
    return (k & ~7) + ((k & 3) << 1) + ((k & 7) >> 2);
}
// k16-perm (fp16 path): within 16-group, logical (2lq,2lq+1,2lq+8,2lq+9)
// land at phys 4lq..4lq+3  ->  one LDS.64 per fragment.
__device__ __forceinline__ int kperm16_(int k) {
    return (k & ~15) + 4 * ((k & 7) >> 1) + 2 * ((k >> 3) & 1) + (k & 1);
}

// =========== convert float -> fp16 with k16 permutation (flat) =============
__global__ __launch_bounds__(256)
void cvt_perm_h(const float* __restrict__ in, __half* __restrict__ out,
                int n16) {
    int g = blockIdx.x * 256 + threadIdx.x;
    if (g >= n16) return;
    const float4* src = (const float4*)(in + (size_t)g * 16);
    __half tmp[16];
#pragma unroll
    for (int j4 = 0; j4 < 4; ++j4) {
        float4 v = src[j4];
        float vals[4] = { v.x, v.y, v.z, v.w };
#pragma unroll
        for (int j = 0; j < 4; ++j) {
            int k = j4 * 4 + j;
            int ph = 4 * ((k & 7) >> 1) + 2 * (k >> 3) + (k & 1);
            tmp[ph] = __float2half_rn(vals[j]);
        }
    }
    uint4* dst = (uint4*)(out + (size_t)g * 16);
    dst[0] = ((uint4*)tmp)[0];
    dst[1] = ((uint4*)tmp)[1];
}

// ======================= rope table: cos/sin per (s,i) =====================
__global__ __launch_bounds__(256)
void rope_table(float2* __restrict__ tab) {
    int idx = blockIdx.x * 256 + threadIdx.x;
    int s = idx >> 6, i = idx & 63;
    float inv_freq = exp2f(-(float)(2 * i) * (1.0f / 128.0f)
                           * 13.28771237954945f);
    float sn, cs;
    sincosf((float)s * inv_freq, &sn, &cs);
    tab[idx] = make_float2(cs, sn);
}

// ===== fp16 mma.sync NT GEMM, cp.async 4-stage, ONE sync/tile ==============
// 128x128 CTA tile, BK=32, 8 warps (warp tile 32x64), pitch-48-halves smem
// (48 halves = 24 words: lg*24+2lq mod 32 covers all 32 banks -> LDS.64
//  fragment loads conflict-free). Inputs pre-converted fp16 + k16-perm.
#define GPH 48
#define GSTWH (128 * GPH)       // halves per operand per stage (6144)
#define GSTAGEH (2 * GSTWH)     // A+B per stage (12288 halves = 24576 B)
#define GNSTG 4
#define GEMM_SMEM (GNSTG * GSTAGEH * 2)  // 98304 bytes

__global__ __launch_bounds__(256, 2)
void gemm_f16mma(const __half* __restrict__ A, const __half* __restrict__ Bm,
                 float* __restrict__ C, int M, int N, int K) {
    extern __shared__ __half smh[];
    const uint32_t sb = smem_u32_(smh);

    const int tid  = threadIdx.x;
    const int lane = tid & 31;
    const int wid  = tid >> 5;
    const int wm   = wid & 3;
    const int wn   = wid >> 2;
    const int m0   = blockIdx.y * 128;
    const int n0   = blockIdx.x * 128;
    const int lg   = lane >> 2;
    const int lq   = lane & 3;

    float acc[2][8][4];
#pragma unroll
    for (int mt = 0; mt < 2; ++mt)
#pragma unroll
        for (int nt = 0; nt < 8; ++nt)
#pragma unroll
            for (int j = 0; j < 4; ++j) acc[mt][nt][j] = 0.f;

    // tile copy: 128 rows x 64 B (A) + same (B) = 1024 chunks; 256 thr x 4
    const int row_ld = tid >> 2;     // 0..63 (+64 for second half)
    const int c_ld   = tid & 3;      // 16B chunk within row (8 halves)

    auto ISSUE = [&](int t) {
        const int st = (t & (GNSTG - 1));
        const int k0 = t << 5;
        const uint32_t base = sb + (uint32_t)(st * GSTAGEH) * 2;
#pragma unroll
        for (int i = 0; i < 2; ++i) {
            int row = row_ld + 64 * i;
            uint32_t off = (uint32_t)(row * GPH + c_ld * 8) * 2;
            cpa16_(base + off,
                   A + (size_t)(m0 + row) * K + k0 + c_ld * 8);
            cpa16_(base + (uint32_t)GSTWH * 2 + off,
                   Bm + (size_t)(n0 + row) * K + k0 + c_ld * 8);
        }
        CP_COMMIT();
    };

    auto COMPUTE = [&](int t) {
        const __half* Sa = smh + (t & (GNSTG - 1)) * GSTAGEH;
        const __half* Sb = Sa + GSTWH;
#pragma unroll
        for (int ks = 0; ks < 2; ++ks) {
            uint32_t af[2][4], bf[8][2];
#pragma unroll
            for (int mt = 0; mt < 2; ++mt) {
                const __half* p = Sa + (wm * 32 + mt * 16 + lg) * GPH
                                + ks * 16 + 4 * lq;
                uint2 lo = *(const uint2*)p;              // a0, a2
                uint2 hi = *(const uint2*)(p + 8 * GPH);  // a1, a3
                af[mt][0] = lo.x;
                af[mt][2] = lo.y;
                af[mt][1] = hi.x;
                af[mt][3] = hi.y;
            }
#pragma unroll
            for (int nt = 0; nt < 8; ++nt) {
                const __half* p = Sb + (wn * 64 + nt * 8 + lg) * GPH
                                + ks * 16 + 4 * lq;
                uint2 v = *(const uint2*)p;               // b0, b1
                bf[nt][0] = v.x;
                bf[nt][1] = v.y;
            }
#pragma unroll
            for (int mt = 0; mt < 2; ++mt)
#pragma unroll
                for (int nt = 0; nt < 8; ++nt)
                    mma_f16_(acc[mt][nt], af[mt], bf[nt]);
        }
    };

    const int ntile = K >> 5;
    ISSUE(0);
    ISSUE(1);
    ISSUE(2);
    for (int t = 0; t < ntile; ++t) {
        const int rem = ntile - 1 - t;
        if (rem >= 2)      { CP_WAIT2(); }
        else if (rem == 1) { CP_WAIT1(); }
        else               { CP_WAIT0(); }
        __syncthreads();
        if (t + 3 < ntile) ISSUE(t + 3);
        COMPUTE(t);
    }

#pragma unroll
    for (int mt = 0; mt < 2; ++mt) {
        int r0 = m0 + wm * 32 + mt * 16 + lg;
#pragma unroll
        for (int nt = 0; nt < 8; ++nt) {
            int c = n0 + wn * 64 + nt * 8 + 2 * lq;
            *(float2*)(C + (size_t)r0 * N + c) =
                make_float2(acc[mt][nt][0], acc[mt][nt][1]);
            *(float2*)(C + (size_t)(r0 + 8) * N + c) =
                make_float2(acc[mt][nt][2], acc[mt][nt][3]);
        }
    }
}

// == RMSNorm + RoPE(table) + transpose; q/k written tf32-rounded + k8-perm ==
__global__ __launch_bounds__(256)
void qkv_post(const float* __restrict__ qkv,
              const float* __restrict__ qw, const float* __restrict__ kw,
              const float2* __restrict__ rope,
              float* __restrict__ q_out, float* __restrict__ k_out,
              float* __restrict__ v_out) {
    const int gwarp = blockIdx.x * 8 + (threadIdx.x >> 5);
    const int lane  = threadIdx.x & 31;
    const int h  = gwarp % 24;
    const int bs = gwarp / 24;
    const int s  = bs & (SEQ - 1);
    const int b  = bs >> 11;

    float4 x = *(const float4*)(qkv + (size_t)bs * QKV_OUT + h * HD + 4 * lane);

    if (h < 20) {
        float ss = x.x * x.x + x.y * x.y + x.z * x.z + x.w * x.w;
#pragma unroll
        for (int o = 16; o; o >>= 1) ss += __shfl_xor_sync(~0u, ss, o);
        float rinv = rsqrtf(ss * (1.0f / HD) + 1e-5f);
        const float* wp = (h < 16) ? qw : kw;
        float4 w = *(const float4*)(wp + 4 * lane);
        x.x *= rinv * w.x; x.y *= rinv * w.y;
        x.z *= rinv * w.z; x.w *= rinv * w.w;
        float4 p;
        p.x = __shfl_xor_sync(~0u, x.x, 16);
        p.y = __shfl_xor_sync(~0u, x.y, 16);
        p.z = __shfl_xor_sync(~0u, x.z, 16);
        p.w = __shfl_xor_sync(~0u, x.w, 16);
        const int i0 = 4 * (lane & 15);
        const bool lo = lane < 16;
        float out[4], xv[4] = {x.x, x.y, x.z, x.w}, pv[4] = {p.x, p.y, p.z, p.w};
        const float2* rp = rope + s * 64 + i0;
#pragma unroll
        for (int j = 0; j < 4; ++j) {
            float2 cssn = rp[j];
            float x1 = lo ? xv[j] : pv[j];
            float x2 = lo ? pv[j] : xv[j];
            out[j] = lo ? (x1 * cssn.x - x2 * cssn.y)
                        : (x1 * cssn.y + x2 * cssn.x);
        }
        float* dst = (h < 16)
            ? q_out + (((size_t)b * NH + h) * SEQ + s) * HD
            : k_out + (((size_t)b * NKV + (h - 16)) * SEQ + s) * HD;
#pragma unroll
        for (int j = 0; j < 4; ++j) {
            int d = 4 * lane + j;
            dst[kperm_(d)] = tf32r_(out[j]);
        }
    } else {
        *(float4*)(v_out + (((size_t)b * NKV + (h - 20)) * SEQ + s) * HD + 4 * lane) =
            tf32r4_(x);
    }
}

// ========== gate = sigmoid(x . w_gate[h] + b), w_gate staged in smem =======
#define GATE_SMEM (NH * DMODEL * 4)   // 131072

__global__ __launch_bounds__(256)
void gate_kernel(const float* __restrict__ x, const float* __restrict__ wg,
                 const float* __restrict__ bg, float* __restrict__ gate) {
    extern __shared__ float ws[];
    const int tid = threadIdx.x;
    const int lane = tid & 31;
    const int warp = tid >> 5;
    for (int i = tid; i < NH * DMODEL / 4; i += 256)
        ((float4*)ws)[i] = ((const float4*)wg)[i];
    __syncthreads();

    const int r0 = blockIdx.x * 32;
#pragma unroll 1
    for (int rr = 0; rr < 4; ++rr) {
        const int row = r0 + warp + 8 * rr;
        const float4* xv = (const float4*)(x + (size_t)row * DMODEL);
        float acc[NH];
#pragma unroll
        for (int h = 0; h < NH; ++h) acc[h] = 0.f;
#pragma unroll 4
        for (int it = 0; it < 16; ++it) {
            int i4 = lane + 32 * it;
            float4 a = xv[i4];
#pragma unroll
            for (int h = 0; h < NH; ++h) {
                float4 w = ((const float4*)ws)[h * (DMODEL / 4) + i4];
                acc[h] += a.x * w.x + a.y * w.y + a.z * w.z + a.w * w.w;
            }
        }
#pragma unroll
        for (int h = 0; h < NH; ++h) {
            float v = acc[h];
#pragma unroll
            for (int o = 16; o; o >>= 1) v += __shfl_xor_sync(~0u, v, o);
            if (lane == 0)
                gate[(size_t)row * NH + h] =
                    1.0f / (1.0f + __expf(-(v + bg[h])));
        }
    }
}

// == causal flash attention (tf32 mma, k8-perm Q/K, cp.async; R15-proven) ===
// CTA: 64 q x 64 kv, 4 warps; 2 CTAs/SM. Epilogue writes fp16 k16-perm attn.
#define FBM 64
#define FBN 64
#define FQP 136
#define FKP 136
#define FVP 136
#define FLASH_SMEM ((FBM*FQP + FBN*FKP + FBN*FVP) * 4)   // 104448 B

__global__ __launch_bounds__(128, 2)
void flash_mma(const float* __restrict__ Q, const float* __restrict__ Kt,
               const float* __restrict__ V, const float* __restrict__ gate,
               __half* __restrict__ Oout) {
    extern __shared__ float sm[];
    float* Qs = sm;                       // [64][136]  (q, hd k8-perm)
    float* Ks = Qs + FBM * FQP;           // [64][136]  (kv, hd k8-perm)
    float* Vs = Ks + FBN * FKP;           // [64][136]  (kv, hd natural)
    const uint32_t sQ = smem_u32_(Qs);
    const uint32_t sK = smem_u32_(Ks);
    const uint32_t sV = smem_u32_(Vs);

    const int qt = blockIdx.x;
    const int h  = blockIdx.y;
    const int b  = blockIdx.z;
    const int kvh = h >> 2;
    const int tid = threadIdx.x;
    const int lane = tid & 31;
    const int w = tid >> 5;
    const int lg = lane >> 2;
    const int lq = lane & 3;
    const int q0 = qt * FBM;

    const float* Qg = Q  + (((size_t)b * NH + h) * SEQ + q0) * HD;
    const float* Kg = Kt + ((size_t)b * NKV + kvh) * SEQ * HD;
    const float* Vg = V  + ((size_t)b * NKV + kvh) * SEQ * HD;

    auto ISSUE_KV = [&](int t) {
        const int k0 = t * FBN;
#pragma unroll
        for (int i = 0; i < 16; ++i) {
            int idx = tid + 128 * i;
            int row = idx >> 5, c4 = idx & 31;
            cpa16_(sK + (uint32_t)(row * FKP + 4 * c4) * 4,
                   Kg + (size_t)(k0 + row) * HD + 4 * c4);
        }
#pragma unroll
        for (int i = 0; i < 16; ++i) {
            int idx = tid + 128 * i;
            int row = idx >> 5, c4 = idx & 31;
            cpa16_(sV + (uint32_t)(row * FVP + 4 * c4) * 4,
                   Vg + (size_t)(k0 + row) * HD + 4 * c4);
        }
        CP_COMMIT();
    };

    // prologue: Q + first K/V tile
    {
#pragma unroll
        for (int i = 0; i < 16; ++i) {
            int idx = tid + 128 * i;
            int row = idx >> 5, c4 = idx & 31;
            cpa16_(sQ + (uint32_t)(row * FQP + 4 * c4) * 4,
                   Qg + (size_t)row * HD + 4 * c4);
        }
        CP_COMMIT();
        ISSUE_KV(0);
        CP_WAIT0();
        __syncthreads();
    }

    float mi[2] = { -1e30f, -1e30f }, li[2] = { 0.f, 0.f };
    float o[16][4];
#pragma unroll
    for (int nt = 0; nt < 16; ++nt)
#pragma unroll
        for (int j = 0; j < 4; ++j) o[nt][j] = 0.f;

    const float scl = 0.08838834764831845f;   // 1/sqrt(128)
    const int nkt = qt + 1;

    for (int t = 0; t < nkt; ++t) {
        const int k0 = t * FBN;

        // ---- S = Q K^T (k8-perm float2 fragment loads) ----
        float sc[8][4];
#pragma unroll
        for (int nt = 0; nt < 8; ++nt)
#pragma unroll
            for (int j = 0; j < 4; ++j) sc[nt][j] = 0.f;

#pragma unroll
        for (int ks = 0; ks < 16; ++ks) {
            const float* pa = Qs + (16 * w + lg) * FQP + 8 * ks + 2 * lq;
            float2 alo = *(const float2*)pa;
            float2 ahi = *(const float2*)(pa + 8 * FQP);
            uint32_t a[4];
            a[0] = __float_as_uint(alo.x);
            a[2] = __float_as_uint(alo.y);
            a[1] = __float_as_uint(ahi.x);
            a[3] = __float_as_uint(ahi.y);
#pragma unroll
            for (int nt = 0; nt < 8; ++nt) {
                const float* pb = Ks + (8 * nt + lg) * FKP + 8 * ks + 2 * lq;
                float2 bv = *(const float2*)pb;
                uint32_t bf[2];
                bf[0] = __float_as_uint(bv.x);
                bf[1] = __float_as_uint(bv.y);
                mma_tf32_(sc[nt], a, bf);
            }
        }

        // ---- scale + causal mask (only diagonal tile t == qt) ----
        const int qr0 = q0 + 16 * w + lg;
        const int qr1 = qr0 + 8;
        const bool needmask = (t == qt);
#pragma unroll
        for (int nt = 0; nt < 8; ++nt) {
            int c0 = k0 + 8 * nt + 2 * lq, c1 = c0 + 1;
            float s0 = sc[nt][0] * scl, s1 = sc[nt][1] * scl;
            float s2 = sc[nt][2] * scl, s3 = sc[nt][3] * scl;
            if (needmask) {
                if (c0 > qr0) s0 = -1e30f;
                if (c1 > qr0) s1 = -1e30f;
                if (c0 > qr1) s2 = -1e30f;
                if (c1 > qr1) s3 = -1e30f;
            }
            sc[nt][0] = s0; sc[nt][1] = s1; sc[nt][2] = s2; sc[nt][3] = s3;
        }

        // ---- online softmax ----
#pragma unroll
        for (int r = 0; r < 2; ++r) {
            float m = -1e30f;
#pragma unroll
            for (int nt = 0; nt < 8; ++nt)
                m = fmaxf(m, fmaxf(sc[nt][2 * r], sc[nt][2 * r + 1]));
            m = fmaxf(m, __shfl_xor_sync(~0u, m, 1));
            m = fmaxf(m, __shfl_xor_sync(~0u, m, 2));
            float newm = fmaxf(mi[r], m);
            float esc = __expf(mi[r] - newm);
            mi[r] = newm;
            float rs = 0.f;
#pragma unroll
            for (int nt = 0; nt < 8; ++nt) {
                float p0 = __expf(sc[nt][2 * r]     - newm);
                float p1 = __expf(sc[nt][2 * r + 1] - newm);
                sc[nt][2 * r] = p0; sc[nt][2 * r + 1] = p1;
                rs += p0 + p1;
            }
            rs += __shfl_xor_sync(~0u, rs, 1);
            rs += __shfl_xor_sync(~0u, rs, 2);
            li[r] = li[r] * esc + rs;
#pragma unroll
            for (int nt = 0; nt < 16; ++nt) {
                o[nt][2 * r]     *= esc;
                o[nt][2 * r + 1] *= esc;
            }
        }

        // ---- O += P V  (P frags via shuffles; V natural [kv][136]) ----
        const int src0 = (lane & ~3) | (lq >> 1);
        const int src1 = src0 + 2;
        const bool odd = lq & 1;
#pragma unroll
        for (int j = 0; j < 8; ++j) {
            float p00 = __shfl_sync(~0u, sc[j][0], src0);
            float p01 = __shfl_sync(~0u, sc[j][1], src0);
            float p02 = __shfl_sync(~0u, sc[j][2], src0);
            float p03 = __shfl_sync(~0u, sc[j][3], src0);
            float q00 = __shfl_sync(~0u, sc[j][0], src1);
            float q01 = __shfl_sync(~0u, sc[j][1], src1);
            float q02 = __shfl_sync(~0u, sc[j][2], src1);
            float q03 = __shfl_sync(~0u, sc[j][3], src1);
            uint32_t a[4];
            a[0] = __float_as_uint(tf32r_(odd ? p01 : p00));
            a[1] = __float_as_uint(tf32r_(odd ? p03 : p02));
            a[2] = __float_as_uint(tf32r_(odd ? q01 : q00));
            a[3] = __float_as_uint(tf32r_(odd ? q03 : q02));
            const float* pv0 = Vs + (8 * j + lq) * FVP + lg;
#pragma unroll
            for (int nt = 0; nt < 16; ++nt) {
                uint32_t bf[2];
                bf[0] = __float_as_uint(pv0[8 * nt]);
                bf[1] = __float_as_uint(pv0[4 * FVP + 8 * nt]);
                mma_tf32_(o[nt], a, bf);
            }
        }

        if (t + 1 < nkt) {
            __syncthreads();
            ISSUE_KV(t + 1);
            CP_WAIT0();
            __syncthreads();
        }
    }

    // ---- epilogue: /li, *gate, fp16 k16-perm scatter to attn ----
#pragma unroll
    for (int r = 0; r < 2; ++r) {
        int row = q0 + 16 * w + lg + 8 * r;
        float g = gate[((size_t)b * SEQ + row) * NH + h];
        float inv = g / li[r];
        __half* dst = Oout + ((size_t)(b * SEQ + row)) * (NH * HD) + h * HD;
#pragma unroll
        for (int nt = 0; nt < 16; ++nt) {
            int c0 = 8 * nt + 2 * lq, c1 = c0 + 1;
            dst[kperm16_(c0)] = __float2half_rn(o[nt][2 * r] * inv);
            dst[kperm16_(c1)] = __float2half_rn(o[nt][2 * r + 1] * inv);
        }
    }
}

// ================================ launch ===================================
extern "C" void kernel_launch(void* const* d_in, const int* in_sizes, int n_in,
                              void* d_out, int out_size) {
    const float* x      = (const float*)d_in[0];
    const float* w_qkv  = (const float*)d_in[1];
    const float* qnw    = (const float*)d_in[2];
    const float* knw    = (const float*)d_in[3];
    const float* w_gate = (const float*)d_in[4];
    const float* b_gate = (const float*)d_in[5];
    const float* w_o    = (const float*)d_in[6];
    float* out = (float*)d_out;

    float *qkv, *q, *k, *v, *gate;
    __half *attnh, *xh, *wqkvh, *woh;
    float2* rope;
    cudaGetSymbolAddress((void**)&qkv,   g_qkv);
    cudaGetSymbolAddress((void**)&q,     g_q);
    cudaGetSymbolAddress((void**)&k,     g_k);
    cudaGetSymbolAddress((void**)&v,     g_v);
    cudaGetSymbolAddress((void**)&gate,  g_gate);
    cudaGetSymbolAddress((void**)&attnh, g_attnh);
    cudaGetSymbolAddress((void**)&rope,  g_rope);
    cudaGetSymbolAddress((void**)&xh,    g_xh);
    cudaGetSymbolAddress((void**)&wqkvh, g_wqkvh);
    cudaGetSymbolAddress((void**)&woh,   g_woh);

    cudaFuncSetAttribute(gemm_f16mma,
                         cudaFuncAttributeMaxDynamicSharedMemorySize, GEMM_SMEM);
    cudaFuncSetAttribute(flash_mma,
                         cudaFuncAttributeMaxDynamicSharedMemorySize, FLASH_SMEM);
    cudaFuncSetAttribute(gate_kernel,
                         cudaFuncAttributeMaxDynamicSharedMemorySize, GATE_SMEM);

    // 0) prep: rope table + fp16/k16-perm GEMM operands
    rope_table<<<SEQ * 64 / 256, 256>>>(rope);
    cvt_perm_h<<<(BSTOT * DMODEL / 16) / 256, 256>>>(x, xh,
                                                     BSTOT * DMODEL / 16);
    cvt_perm_h<<<(QKV_OUT * DMODEL / 16) / 256, 256>>>(w_qkv, wqkvh,
                                                       QKV_OUT * DMODEL / 16);
    cvt_perm_h<<<(DMODEL * DMODEL / 16) / 256, 256>>>(w_o, woh,
                                                      DMODEL * DMODEL / 16);
    // 1) QKV projection: [4096,2048] x [3072,2048]^T (fp16 mma)
    {
        dim3 grid(QKV_OUT / 128, BSTOT / 128);
        gemm_f16mma<<<grid, 256, GEMM_SMEM>>>(xh, wqkvh, qkv,
                                              BSTOT, QKV_OUT, DMODEL);
    }
    // 2) RMSNorm + RoPE(table) + layout (q/k tf32-rounded + k8-perm)
    {
        qkv_post<<<(BSTOT * 24) / 8, 256>>>(qkv, qnw, knw, rope, q, k, v);
    }
    // 3) gate (w_gate staged in smem; reads original x)
    {
        gate_kernel<<<BSTOT / 32, 256, GATE_SMEM>>>(x, w_gate, b_gate, gate);
    }
    // 4) flash attention, tf32 mma (gated epilogue -> fp16 k16-perm attn)
    {
        dim3 grid(SEQ / FBM, NH, BATCH);
        flash_mma<<<grid, 128, FLASH_SMEM>>>(q, k, v, gate, attnh);
    }
    // 5) output projection: [4096,2048] x [2048,2048]^T -> d_out (fp16 mma)
    {
        dim3 grid(DMODEL / 128, BSTOT / 128);
        gemm_f16mma<<<grid, 256, GEMM_SMEM>>>(attnh, woh, out,
                                              BSTOT, DMODEL, DMODEL);
    }
}

// round 17
// speedup vs baseline: 2.0589x; 1.2171x over previous
#include <cuda_runtime.h>
#include <cuda_fp16.h>
#include <cuda_bf16.h>
#include <math.h>
#include <cstdint>

#define BATCH 2
#define SEQ 2048
#define DMODEL 2048
#define NH 16
#define NKV 4
#define HD 128
#define NREP 4
#define QKV_OUT 3072   // (16 + 2*4) * 128
#define BSTOT (BATCH*SEQ)

// ---------------- scratch (device globals; no allocation allowed) ----------
__device__ float  g_qkv  [BSTOT * QKV_OUT];        // 48 MB
__device__ __half g_qh   [BATCH * NH  * SEQ * HD]; // 16 MB (fp16, k16-perm hd)
__device__ __half g_kh   [BATCH * NKV * SEQ * HD]; //  4 MB (fp16, k16-perm hd)
__device__ __half g_vh   [BATCH * NKV * SEQ * HD]; //  4 MB (fp16, natural)
__device__ __half g_vt   [BATCH * NKV * HD * SEQ]; //  4 MB (fp16, [hd][s-perm])
__device__ float  g_gate [BSTOT * NH];             // 0.5 MB
__device__ __half g_attnh[BSTOT * (NH*HD)];        // 16 MB (fp16, k16-perm)
__device__ float2 g_rope [SEQ * 64];               // 1 MB
__device__ __half g_xh   [BSTOT * DMODEL];         // 16 MB (fp16, k16-perm)
__device__ __half g_wqkvh[QKV_OUT * DMODEL];       // 12 MB (fp16, k16-perm)
__device__ __half g_woh  [DMODEL * DMODEL];        //  8 MB (fp16, k16-perm)

// ========================== helpers ========================================
__device__ __forceinline__ uint32_t smem_u32_(const void* p) {
    uint32_t a;
    asm("{ .reg .u64 t; cvta.to.shared.u64 t, %1; cvt.u32.u64 %0, t; }"
        : "=r"(a) : "l"(p));
    return a;
}
__device__ __forceinline__ void cpa16_(uint32_t dst, const void* src) {
    asm volatile("cp.async.cg.shared.global [%0], [%1], 16;"
                 :: "r"(dst), "l"(src));
}
#define CP_COMMIT() asm volatile("cp.async.commit_group;" ::: "memory")
#define CP_WAIT0()  asm volatile("cp.async.wait_group 0;" ::: "memory")
#define CP_WAIT1()  asm volatile("cp.async.wait_group 1;" ::: "memory")
#define CP_WAIT2()  asm volatile("cp.async.wait_group 2;" ::: "memory")

// fp16: D(f32) += A(16x16,row,f16) * B(16x8,col,f16)
__device__ __forceinline__ void mma_f16_(float* d, const uint32_t* a,
                                         const uint32_t* b) {
    asm volatile(
        "mma.sync.aligned.m16n8k16.row.col.f32.f16.f16.f32 "
        "{%0,%1,%2,%3}, {%4,%5,%6,%7}, {%8,%9}, {%0,%1,%2,%3};\n"
        : "+f"(d[0]), "+f"(d[1]), "+f"(d[2]), "+f"(d[3])
        : "r"(a[0]), "r"(a[1]), "r"(a[2]), "r"(a[3]),
          "r"(b[0]), "r"(b[1]));
}

// k16-perm: within 16-group, logical (2q,2q+1,2q+8,2q+9) -> phys 4q..4q+3.
__device__ __forceinline__ int kperm16_(int k) {
    return (k & ~15) + 4 * ((k & 7) >> 1) + 2 * ((k >> 3) & 1) + (k & 1);
}
// inverse (phys p in 0..15 -> logical k)
__device__ __forceinline__ int kperm16inv_(int p) {
    return (p & ~15) + 8 * ((p >> 1) & 1) + 2 * ((p & 15) >> 2) + (p & 1);
}
__device__ __forceinline__ uint32_t packh2_(float lo, float hi) {
    __half2 h = __floats2half2_rn(lo, hi);
    return *(uint32_t*)&h;
}

// =========== convert float -> fp16 with k16 permutation (flat) =============
__global__ __launch_bounds__(256)
void cvt_perm_h(const float* __restrict__ in, __half* __restrict__ out,
                int n16) {
    int g = blockIdx.x * 256 + threadIdx.x;
    if (g >= n16) return;
    const float4* src = (const float4*)(in + (size_t)g * 16);
    __half tmp[16];
#pragma unroll
    for (int j4 = 0; j4 < 4; ++j4) {
        float4 v = src[j4];
        float vals[4] = { v.x, v.y, v.z, v.w };
#pragma unroll
        for (int j = 0; j < 4; ++j) {
            int k = j4 * 4 + j;
            int ph = 4 * ((k & 7) >> 1) + 2 * (k >> 3) + (k & 1);
            tmp[ph] = __float2half_rn(vals[j]);
        }
    }
    uint4* dst = (uint4*)(out + (size_t)g * 16);
    dst[0] = ((uint4*)tmp)[0];
    dst[1] = ((uint4*)tmp)[1];
}

// ======================= rope table: cos/sin per (s,i) =====================
__global__ __launch_bounds__(256)
void rope_table(float2* __restrict__ tab) {
    int idx = blockIdx.x * 256 + threadIdx.x;
    int s = idx >> 6, i = idx & 63;
    float inv_freq = exp2f(-(float)(2 * i) * (1.0f / 128.0f)
                           * 13.28771237954945f);
    float sn, cs;
    sincosf((float)s * inv_freq, &sn, &cs);
    tab[idx] = make_float2(cs, sn);
}

// ===== fp16 mma.sync NT GEMM, cp.async 4-stage, ONE sync/tile (R16) ========
#define GPH 48
#define GSTWH (128 * GPH)
#define GSTAGEH (2 * GSTWH)
#define GNSTG 4
#define GEMM_SMEM (GNSTG * GSTAGEH * 2)  // 98304 bytes

__global__ __launch_bounds__(256, 2)
void gemm_f16mma(const __half* __restrict__ A, const __half* __restrict__ Bm,
                 float* __restrict__ C, int M, int N, int K) {
    extern __shared__ __half smh[];
    const uint32_t sb = smem_u32_(smh);

    const int tid  = threadIdx.x;
    const int lane = tid & 31;
    const int wid  = tid >> 5;
    const int wm   = wid & 3;
    const int wn   = wid >> 2;
    const int m0   = blockIdx.y * 128;
    const int n0   = blockIdx.x * 128;
    const int lg   = lane >> 2;
    const int lq   = lane & 3;

    float acc[2][8][4];
#pragma unroll
    for (int mt = 0; mt < 2; ++mt)
#pragma unroll
        for (int nt = 0; nt < 8; ++nt)
#pragma unroll
            for (int j = 0; j < 4; ++j) acc[mt][nt][j] = 0.f;

    const int row_ld = tid >> 2;
    const int c_ld   = tid & 3;

    auto ISSUE = [&](int t) {
        const int st = (t & (GNSTG - 1));
        const int k0 = t << 5;
        const uint32_t base = sb + (uint32_t)(st * GSTAGEH) * 2;
#pragma unroll
        for (int i = 0; i < 2; ++i) {
            int row = row_ld + 64 * i;
            uint32_t off = (uint32_t)(row * GPH + c_ld * 8) * 2;
            cpa16_(base + off,
                   A + (size_t)(m0 + row) * K + k0 + c_ld * 8);
            cpa16_(base + (uint32_t)GSTWH * 2 + off,
                   Bm + (size_t)(n0 + row) * K + k0 + c_ld * 8);
        }
        CP_COMMIT();
    };

    auto COMPUTE = [&](int t) {
        const __half* Sa = smh + (t & (GNSTG - 1)) * GSTAGEH;
        const __half* Sb = Sa + GSTWH;
#pragma unroll
        for (int ks = 0; ks < 2; ++ks) {
            uint32_t af[2][4], bf[8][2];
#pragma unroll
            for (int mt = 0; mt < 2; ++mt) {
                const __half* p = Sa + (wm * 32 + mt * 16 + lg) * GPH
                                + ks * 16 + 4 * lq;
                uint2 lo = *(const uint2*)p;
                uint2 hi = *(const uint2*)(p + 8 * GPH);
                af[mt][0] = lo.x;
                af[mt][2] = lo.y;
                af[mt][1] = hi.x;
                af[mt][3] = hi.y;
            }
#pragma unroll
            for (int nt = 0; nt < 8; ++nt) {
                const __half* p = Sb + (wn * 64 + nt * 8 + lg) * GPH
                                + ks * 16 + 4 * lq;
                uint2 v = *(const uint2*)p;
                bf[nt][0] = v.x;
                bf[nt][1] = v.y;
            }
#pragma unroll
            for (int mt = 0; mt < 2; ++mt)
#pragma unroll
                for (int nt = 0; nt < 8; ++nt)
                    mma_f16_(acc[mt][nt], af[mt], bf[nt]);
        }
    };

    const int ntile = K >> 5;
    ISSUE(0);
    ISSUE(1);
    ISSUE(2);
    for (int t = 0; t < ntile; ++t) {
        const int rem = ntile - 1 - t;
        if (rem >= 2)      { CP_WAIT2(); }
        else if (rem == 1) { CP_WAIT1(); }
        else               { CP_WAIT0(); }
        __syncthreads();
        if (t + 3 < ntile) ISSUE(t + 3);
        COMPUTE(t);
    }

#pragma unroll
    for (int mt = 0; mt < 2; ++mt) {
        int r0 = m0 + wm * 32 + mt * 16 + lg;
#pragma unroll
        for (int nt = 0; nt < 8; ++nt) {
            int c = n0 + wn * 64 + nt * 8 + 2 * lq;
            *(float2*)(C + (size_t)r0 * N + c) =
                make_float2(acc[mt][nt][0], acc[mt][nt][1]);
            *(float2*)(C + (size_t)(r0 + 8) * N + c) =
                make_float2(acc[mt][nt][2], acc[mt][nt][3]);
        }
    }
}

// == RMSNorm + RoPE(table) + transpose; q/k fp16 k16-perm, v fp16 natural ===
__global__ __launch_bounds__(256)
void qkv_post(const float* __restrict__ qkv,
              const float* __restrict__ qw, const float* __restrict__ kw,
              const float2* __restrict__ rope,
              __half* __restrict__ q_out, __half* __restrict__ k_out,
              __half* __restrict__ v_out) {
    const int gwarp = blockIdx.x * 8 + (threadIdx.x >> 5);
    const int lane  = threadIdx.x & 31;
    const int h  = gwarp % 24;
    const int bs = gwarp / 24;
    const int s  = bs & (SEQ - 1);
    const int b  = bs >> 11;

    float4 x = *(const float4*)(qkv + (size_t)bs * QKV_OUT + h * HD + 4 * lane);

    if (h < 20) {
        float ss = x.x * x.x + x.y * x.y + x.z * x.z + x.w * x.w;
#pragma unroll
        for (int o = 16; o; o >>= 1) ss += __shfl_xor_sync(~0u, ss, o);
        float rinv = rsqrtf(ss * (1.0f / HD) + 1e-5f);
        const float* wp = (h < 16) ? qw : kw;
        float4 w = *(const float4*)(wp + 4 * lane);
        x.x *= rinv * w.x; x.y *= rinv * w.y;
        x.z *= rinv * w.z; x.w *= rinv * w.w;
        float4 p;
        p.x = __shfl_xor_sync(~0u, x.x, 16);
        p.y = __shfl_xor_sync(~0u, x.y, 16);
        p.z = __shfl_xor_sync(~0u, x.z, 16);
        p.w = __shfl_xor_sync(~0u, x.w, 16);
        const int i0 = 4 * (lane & 15);
        const bool lo = lane < 16;
        float out[4], xv[4] = {x.x, x.y, x.z, x.w}, pv[4] = {p.x, p.y, p.z, p.w};
        const float2* rp = rope + s * 64 + i0;
#pragma unroll
        for (int j = 0; j < 4; ++j) {
            float2 cssn = rp[j];
            float x1 = lo ? xv[j] : pv[j];
            float x2 = lo ? pv[j] : xv[j];
            out[j] = lo ? (x1 * cssn.x - x2 * cssn.y)
                        : (x1 * cssn.y + x2 * cssn.x);
        }
        __half* dst = (h < 16)
            ? q_out + (((size_t)b * NH + h) * SEQ + s) * HD
            : k_out + (((size_t)b * NKV + (h - 16)) * SEQ + s) * HD;
#pragma unroll
        for (int j = 0; j < 4; ++j) {
            int d = 4 * lane + j;
            dst[kperm16_(d)] = __float2half_rn(out[j]);
        }
    } else {
        __half* dst = v_out + (((size_t)b * NKV + (h - 20)) * SEQ + s) * HD
                    + 4 * lane;
        __half tmp[4] = { __float2half_rn(x.x), __float2half_rn(x.y),
                          __float2half_rn(x.z), __float2half_rn(x.w) };
        *(uint2*)dst = *(uint2*)tmp;
    }
}

// ========= V transpose: [s][hd] fp16 -> [hd][s k16-perm] fp16 ==============
// grid (SEQ/64, HD/64, BATCH*NKV), block 256.
__global__ __launch_bounds__(256)
void v_transpose(const __half* __restrict__ vin, __half* __restrict__ vout) {
    __shared__ __half tile[64][72];
    const int s0  = blockIdx.x * 64;
    const int hd0 = blockIdx.y * 64;
    const int z   = blockIdx.z;
    const int tid = threadIdx.x;

    const __half* src = vin + ((size_t)z * SEQ + s0) * HD + hd0;
#pragma unroll
    for (int i = 0; i < 2; ++i) {
        int lin = tid + 256 * i;         // 0..511 chunks of 8
        int row = lin >> 3, c = lin & 7;
        *(uint4*)&tile[row][8 * c] = *(const uint4*)(src + (size_t)row * HD + 8 * c);
    }
    __syncthreads();

    __half* dst = vout + ((size_t)z * HD + hd0) * SEQ + s0;
#pragma unroll
    for (int i = 0; i < 2; ++i) {
        int lin = tid + 256 * i;
        int r = lin >> 3, ch = lin & 7;  // out row hd=r, 8-half chunk ch
        __half vals[8];
#pragma unroll
        for (int e = 0; e < 8; ++e) {
            int p = 8 * ch + e;          // phys s position in 0..63
            int pi = p & 15, grp = p >> 4;
            int slog = 16 * grp + 8 * ((pi >> 1) & 1) + 2 * (pi >> 2) + (pi & 1);
            vals[e] = tile[slog][r];
        }
        *(uint4*)(dst + (size_t)r * SEQ + 8 * ch) = *(uint4*)vals;
    }
}

// ========== gate = sigmoid(x . w_gate[h] + b), w_gate staged in smem =======
#define GATE_SMEM (NH * DMODEL * 4)   // 131072

__global__ __launch_bounds__(256)
void gate_kernel(const float* __restrict__ x, const float* __restrict__ wg,
                 const float* __restrict__ bg, float* __restrict__ gate) {
    extern __shared__ float ws[];
    const int tid = threadIdx.x;
    const int lane = tid & 31;
    const int warp = tid >> 5;
    for (int i = tid; i < NH * DMODEL / 4; i += 256)
        ((float4*)ws)[i] = ((const float4*)wg)[i];
    __syncthreads();

    const int r0 = blockIdx.x * 32;
#pragma unroll 1
    for (int rr = 0; rr < 4; ++rr) {
        const int row = r0 + warp + 8 * rr;
        const float4* xv = (const float4*)(x + (size_t)row * DMODEL);
        float acc[NH];
#pragma unroll
        for (int h = 0; h < NH; ++h) acc[h] = 0.f;
#pragma unroll 4
        for (int it = 0; it < 16; ++it) {
            int i4 = lane + 32 * it;
            float4 a = xv[i4];
#pragma unroll
            for (int h = 0; h < NH; ++h) {
                float4 w = ((const float4*)ws)[h * (DMODEL / 4) + i4];
                acc[h] += a.x * w.x + a.y * w.y + a.z * w.z + a.w * w.w;
            }
        }
#pragma unroll
        for (int h = 0; h < NH; ++h) {
            float v = acc[h];
#pragma unroll
            for (int o = 16; o; o >>= 1) v += __shfl_xor_sync(~0u, v, o);
            if (lane == 0)
                gate[(size_t)row * NH + h] =
                    1.0f / (1.0f + __expf(-(v + bg[h])));
        }
    }
}

// ====== causal flash attention, FULL fp16 mma (Q/K k16-perm, Vt) ===========
// CTA: 64 q x 64 kv, 4 warps; 2 CTAs/SM; smem 57344 B.
#define FBM 64
#define FBN 64
#define FQPH 144     // halves (72 words; 8lg+2lq pattern conflict-free)
#define FKPH 144
#define FVPH 80      // halves (40 words; same pattern)
#define FLASH_SMEM ((FBM*FQPH + FBN*FKPH + HD*FVPH) * 2)   // 57344 B

__global__ __launch_bounds__(128, 2)
void flash_mma(const __half* __restrict__ Q, const __half* __restrict__ Kt,
               const __half* __restrict__ Vt, const float* __restrict__ gate,
               __half* __restrict__ Oout) {
    extern __shared__ __half smf[];
    __half* Qs = smf;                      // [64][144]  (q, hd k16-perm)
    __half* Ks = Qs + FBM * FQPH;          // [64][144]  (kv, hd k16-perm)
    __half* Vs = Ks + FBN * FKPH;          // [128][80]  (hd, kv k16-perm)
    const uint32_t sQ = smem_u32_(Qs);
    const uint32_t sK = smem_u32_(Ks);
    const uint32_t sV = smem_u32_(Vs);

    const int qt = blockIdx.x;
    const int h  = blockIdx.y;
    const int b  = blockIdx.z;
    const int kvh = h >> 2;
    const int tid = threadIdx.x;
    const int lane = tid & 31;
    const int w = tid >> 5;
    const int lg = lane >> 2;
    const int lq = lane & 3;
    const int q0 = qt * FBM;

    const __half* Qg = Q  + (((size_t)b * NH + h) * SEQ + q0) * HD;
    const __half* Kg = Kt + ((size_t)b * NKV + kvh) * SEQ * HD;
    const __half* Vg = Vt + ((size_t)b * NKV + kvh) * (size_t)HD * SEQ;

    auto ISSUE_KV = [&](int t) {
        const int k0 = t * FBN;
        // K: 64 rows x 16 chunks (8 halves) = 1024; 128 thr x 8
#pragma unroll
        for (int i = 0; i < 8; ++i) {
            int idx = tid + 128 * i;
            int row = idx >> 4, c = idx & 15;
            cpa16_(sK + (uint32_t)(row * FKPH + 8 * c) * 2,
                   Kg + (size_t)(k0 + row) * HD + 8 * c);
        }
        // Vt: 128 rows x 8 chunks = 1024
#pragma unroll
        for (int i = 0; i < 8; ++i) {
            int idx = tid + 128 * i;
            int row = idx >> 3, c = idx & 7;
            cpa16_(sV + (uint32_t)(row * FVPH + 8 * c) * 2,
                   Vg + (size_t)row * SEQ + k0 + 8 * c);
        }
        CP_COMMIT();
    };

    // prologue: Q + first K/V tile
    {
#pragma unroll
        for (int i = 0; i < 8; ++i) {
            int idx = tid + 128 * i;
            int row = idx >> 4, c = idx & 15;
            cpa16_(sQ + (uint32_t)(row * FQPH + 8 * c) * 2,
                   Qg + (size_t)row * HD + 8 * c);
        }
        CP_COMMIT();
        ISSUE_KV(0);
        CP_WAIT0();
        __syncthreads();
    }

    float mi[2] = { -1e30f, -1e30f }, li[2] = { 0.f, 0.f };
    float o[16][4];
#pragma unroll
    for (int nt = 0; nt < 16; ++nt)
#pragma unroll
        for (int j = 0; j < 4; ++j) o[nt][j] = 0.f;

    const float scl = 0.08838834764831845f;   // 1/sqrt(128)
    const int nkt = qt + 1;

    for (int t = 0; t < nkt; ++t) {
        const int k0 = t * FBN;

        // ---- S = Q K^T (fp16, 8 k16-steps) ----
        float sc[8][4];
#pragma unroll
        for (int nt = 0; nt < 8; ++nt)
#pragma unroll
            for (int j = 0; j < 4; ++j) sc[nt][j] = 0.f;

#pragma unroll
        for (int ks = 0; ks < 8; ++ks) {
            const __half* pa = Qs + (16 * w + lg) * FQPH + 16 * ks + 4 * lq;
            uint2 alo = *(const uint2*)pa;
            uint2 ahi = *(const uint2*)(pa + 8 * FQPH);
            uint32_t a[4];
            a[0] = alo.x;
            a[2] = alo.y;
            a[1] = ahi.x;
            a[3] = ahi.y;
#pragma unroll
            for (int nt = 0; nt < 8; ++nt) {
                const __half* pb = Ks + (8 * nt + lg) * FKPH + 16 * ks + 4 * lq;
                uint2 bv = *(const uint2*)pb;
                uint32_t bf[2] = { bv.x, bv.y };
                mma_f16_(sc[nt], a, bf);
            }
        }

        // ---- scale + causal mask (only diagonal tile t == qt) ----
        const int qr0 = q0 + 16 * w + lg;
        const int qr1 = qr0 + 8;
        const bool needmask = (t == qt);
#pragma unroll
        for (int nt = 0; nt < 8; ++nt) {
            int c0 = k0 + 8 * nt + 2 * lq, c1 = c0 + 1;
            float s0 = sc[nt][0] * scl, s1 = sc[nt][1] * scl;
            float s2 = sc[nt][2] * scl, s3 = sc[nt][3] * scl;
            if (needmask) {
                if (c0 > qr0) s0 = -1e30f;
                if (c1 > qr0) s1 = -1e30f;
                if (c0 > qr1) s2 = -1e30f;
                if (c1 > qr1) s3 = -1e30f;
            }
            sc[nt][0] = s0; sc[nt][1] = s1; sc[nt][2] = s2; sc[nt][3] = s3;
        }

        // ---- online softmax ----
#pragma unroll
        for (int r = 0; r < 2; ++r) {
            float m = -1e30f;
#pragma unroll
            for (int nt = 0; nt < 8; ++nt)
                m = fmaxf(m, fmaxf(sc[nt][2 * r], sc[nt][2 * r + 1]));
            m = fmaxf(m, __shfl_xor_sync(~0u, m, 1));
            m = fmaxf(m, __shfl_xor_sync(~0u, m, 2));
            float newm = fmaxf(mi[r], m);
            float esc = __expf(mi[r] - newm);
            mi[r] = newm;
            float rs = 0.f;
#pragma unroll
            for (int nt = 0; nt < 8; ++nt) {
                float p0 = __expf(sc[nt][2 * r]     - newm);
                float p1 = __expf(sc[nt][2 * r + 1] - newm);
                sc[nt][2 * r] = p0; sc[nt][2 * r + 1] = p1;
                rs += p0 + p1;
            }
            rs += __shfl_xor_sync(~0u, rs, 1);
            rs += __shfl_xor_sync(~0u, rs, 2);
            li[r] = li[r] * esc + rs;
#pragma unroll
            for (int nt = 0; nt < 16; ++nt) {
                o[nt][2 * r]     *= esc;
                o[nt][2 * r + 1] *= esc;
            }
        }

        // ---- O += P V  (fp16; P frags packed straight from sc, NO shuffles)
#pragma unroll
        for (int j = 0; j < 4; ++j) {
            uint32_t a[4];
            a[0] = packh2_(sc[2 * j][0],     sc[2 * j][1]);
            a[1] = packh2_(sc[2 * j][2],     sc[2 * j][3]);
            a[2] = packh2_(sc[2 * j + 1][0], sc[2 * j + 1][1]);
            a[3] = packh2_(sc[2 * j + 1][2], sc[2 * j + 1][3]);
#pragma unroll
            for (int nt = 0; nt < 16; ++nt) {
                const __half* pb = Vs + (8 * nt + lg) * FVPH + 16 * j + 4 * lq;
                uint2 bv = *(const uint2*)pb;
                uint32_t bf[2] = { bv.x, bv.y };
                mma_f16_(o[nt], a, bf);
            }
        }

        if (t + 1 < nkt) {
            __syncthreads();
            ISSUE_KV(t + 1);
            CP_WAIT0();
            __syncthreads();
        }
    }

    // ---- epilogue: /li, *gate, fp16 k16-perm scatter to attn ----
#pragma unroll
    for (int r = 0; r < 2; ++r) {
        int row = q0 + 16 * w + lg + 8 * r;
        float g = gate[((size_t)b * SEQ + row) * NH + h];
        float inv = g / li[r];
        __half* dst = Oout + ((size_t)(b * SEQ + row)) * (NH * HD) + h * HD;
#pragma unroll
        for (int nt = 0; nt < 16; ++nt) {
            int c0 = 8 * nt + 2 * lq, c1 = c0 + 1;
            dst[kperm16_(c0)] = __float2half_rn(o[nt][2 * r] * inv);
            dst[kperm16_(c1)] = __float2half_rn(o[nt][2 * r + 1] * inv);
        }
    }
}

// ================================ launch ===================================
extern "C" void kernel_launch(void* const* d_in, const int* in_sizes, int n_in,
                              void* d_out, int out_size) {
    const float* x      = (const float*)d_in[0];
    const float* w_qkv  = (const float*)d_in[1];
    const float* qnw    = (const float*)d_in[2];
    const float* knw    = (const float*)d_in[3];
    const float* w_gate = (const float*)d_in[4];
    const float* b_gate = (const float*)d_in[5];
    const float* w_o    = (const float*)d_in[6];
    float* out = (float*)d_out;

    float *qkv, *gate;
    __half *qh, *kh, *vh, *vt, *attnh, *xh, *wqkvh, *woh;
    float2* rope;
    cudaGetSymbolAddress((void**)&qkv,   g_qkv);
    cudaGetSymbolAddress((void**)&qh,    g_qh);
    cudaGetSymbolAddress((void**)&kh,    g_kh);
    cudaGetSymbolAddress((void**)&vh,    g_vh);
    cudaGetSymbolAddress((void**)&vt,    g_vt);
    cudaGetSymbolAddress((void**)&gate,  g_gate);
    cudaGetSymbolAddress((void**)&attnh, g_attnh);
    cudaGetSymbolAddress((void**)&rope,  g_rope);
    cudaGetSymbolAddress((void**)&xh,    g_xh);
    cudaGetSymbolAddress((void**)&wqkvh, g_wqkvh);
    cudaGetSymbolAddress((void**)&woh,   g_woh);

    cudaFuncSetAttribute(gemm_f16mma,
                         cudaFuncAttributeMaxDynamicSharedMemorySize, GEMM_SMEM);
    cudaFuncSetAttribute(flash_mma,
                         cudaFuncAttributeMaxDynamicSharedMemorySize, FLASH_SMEM);
    cudaFuncSetAttribute(gate_kernel,
                         cudaFuncAttributeMaxDynamicSharedMemorySize, GATE_SMEM);

    // 0) prep: rope table + fp16/k16-perm GEMM operands
    rope_table<<<SEQ * 64 / 256, 256>>>(rope);
    cvt_perm_h<<<(BSTOT * DMODEL / 16) / 256, 256>>>(x, xh,
                                                     BSTOT * DMODEL / 16);
    cvt_perm_h<<<(QKV_OUT * DMODEL / 16) / 256, 256>>>(w_qkv, wqkvh,
                                                       QKV_OUT * DMODEL / 16);
    cvt_perm_h<<<(DMODEL * DMODEL / 16) / 256, 256>>>(w_o, woh,
                                                      DMODEL * DMODEL / 16);
    // 1) QKV projection (fp16 mma)
    {
        dim3 grid(QKV_OUT / 128, BSTOT / 128);
        gemm_f16mma<<<grid, 256, GEMM_SMEM>>>(xh, wqkvh, qkv,
                                              BSTOT, QKV_OUT, DMODEL);
    }
    // 2) RMSNorm + RoPE(table) + layout (q/k fp16 k16-perm, v fp16 natural)
    {
        qkv_post<<<(BSTOT * 24) / 8, 256>>>(qkv, qnw, knw, rope, qh, kh, vh);
    }
    // 2b) V transpose -> [hd][s k16-perm]
    {
        dim3 grid(SEQ / 64, HD / 64, BATCH * NKV);
        v_transpose<<<grid, 256>>>(vh, vt);
    }
    // 3) gate (w_gate staged in smem; reads original x)
    {
        gate_kernel<<<BSTOT / 32, 256, GATE_SMEM>>>(x, w_gate, b_gate, gate);
    }
    // 4) flash attention, full fp16 mma (gated epilogue -> fp16 k16-perm attn)
    {
        dim3 grid(SEQ / FBM, NH, BATCH);
        flash_mma<<<grid, 128, FLASH_SMEM>>>(qh, kh, vt, gate, attnh);
    }
    // 5) output projection -> d_out (fp16 mma)
    {
        dim3 grid(DMODEL / 128, BSTOT / 128);
        gemm_f16mma<<<grid, 256, GEMM_SMEM>>>(attnh, woh, out,
                                              BSTOT, DMODEL, DMODEL);
    }
}